// round 1
// baseline (speedup 1.0000x reference)
#include <cuda_runtime.h>
#include <math.h>

#define BB 256
#define SS 512
#define RR 128
#define HH 512
#define TT 96
#define GG 2048   // 4*H
#define K2 1024   // 2*H

// ---------------- device scratch (allocation-free: module globals) ----------------
__device__ float g_hs[SS * BB * HH];        // encoder hidden states [s][b][h] (256 MB)
__device__ float g_hbuf[2][BB * HH];        // ping-pong hidden state
__device__ float g_c[BB * HH];              // cell state (thread-owned, in-place)
__device__ float g_v[GG], g_u[GG], g_bd[GG];
__device__ float g_Wdec[GG * K2];           // combined decoder weight [j][k]
__device__ float g_WkT[HH * HH], g_WqT[HH * HH], g_At[HH * HH];
__device__ float g_bqk[HH];
__device__ float g_q2[BB * HH];
__device__ float g_ctx[BB * HH];

// ---------------- prep kernels ----------------
__global__ void k_zero() {
    int idx = blockIdx.x * 256 + threadIdx.x;
    if (idx < BB * HH) { g_hbuf[0][idx] = 0.f; g_c[idx] = 0.f; }
}

// v[j] = sum_r embed_W[r]*Wih[j,r]; u[j] = sum_r embed_b[r]*Wih[j,r] + bih[j] + bhh[j]
__global__ void k_vu(const float* __restrict__ embW, const float* __restrict__ embb,
                     const float* __restrict__ Wih, const float* __restrict__ bih,
                     const float* __restrict__ bhh) {
    int j = blockIdx.x * 256 + threadIdx.x;
    if (j >= GG) return;
    float v = 0.f, u = 0.f;
    const float* wr = Wih + j * RR;
#pragma unroll 8
    for (int r = 0; r < RR; ++r) { v += embW[r] * wr[r]; u += embb[r] * wr[r]; }
    g_v[j] = v;
    g_u[j] = u + bih[j] + bhh[j];
}

// Wdec[j][k] = dec_Wih[j][k] + (k<H ? dec_Whh[j][k] : 0); bd = bih+bhh
__global__ void k_wdec(const float* __restrict__ dWih, const float* __restrict__ dWhh,
                       const float* __restrict__ dbih, const float* __restrict__ dbhh) {
    int idx = blockIdx.x * 256 + threadIdx.x;
    if (idx < GG * K2) {
        int j = idx >> 10, k = idx & (K2 - 1);
        float w = dWih[idx];
        if (k < HH) w += dWhh[j * HH + k];
        g_Wdec[idx] = w;
    }
    if (idx < GG) g_bd[idx] = dbih[idx] + dbhh[idx];
}

// bqk[m] = sum_n bq[n] * Wk[n,m]
__global__ void k_bqk(const float* __restrict__ bq, const float* __restrict__ Wk) {
    int m = blockIdx.x * 256 + threadIdx.x;
    if (m >= HH) return;
    float a = 0.f;
    for (int n = 0; n < HH; ++n) a += bq[n] * Wk[n * HH + m];
    g_bqk[m] = a;
}

// 512x512 transpose
__global__ void k_transpose512(const float* __restrict__ in, float* __restrict__ out) {
    __shared__ float t[32][33];
    int x = blockIdx.x * 32 + threadIdx.x;
    int y0 = blockIdx.y * 32;
    for (int j = threadIdx.y; j < 32; j += 8) t[j][threadIdx.x] = in[(y0 + j) * HH + x];
    __syncthreads();
    int x2 = y0 + threadIdx.x;
    int y20 = blockIdx.x * 32;
    for (int j = threadIdx.y; j < 32; j += 8) out[(y20 + j) * HH + x2] = t[threadIdx.x][j];
}

// ---------------- generic 32x32-tile fp32 GEMM core: C[m][n] = sum_k A[m][k]*Bw[n][k] (+bias[n]) ----------------
__device__ __forceinline__ void gemm32_core(const float* __restrict__ A,
                                            const float* __restrict__ Bw,
                                            const float* __restrict__ bias,
                                            float* __restrict__ C, int N, int K) {
    __shared__ float As[32][33];
    __shared__ float Bs[32][33];
    int tid = threadIdx.x;
    int m0 = blockIdx.y * 32, n0 = blockIdx.x * 32;
    int lr = tid >> 3, lk = (tid & 7) << 2;
    int ty = tid >> 4, tx = tid & 15;
    float acc00 = 0.f, acc01 = 0.f, acc10 = 0.f, acc11 = 0.f;
    for (int kk = 0; kk < K; kk += 32) {
        float4 a = *(const float4*)(A + (m0 + lr) * K + kk + lk);
        float4 b = *(const float4*)(Bw + (n0 + lr) * K + kk + lk);
        __syncthreads();
        As[lk + 0][lr] = a.x; As[lk + 1][lr] = a.y; As[lk + 2][lr] = a.z; As[lk + 3][lr] = a.w;
        Bs[lk + 0][lr] = b.x; Bs[lk + 1][lr] = b.y; Bs[lk + 2][lr] = b.z; Bs[lk + 3][lr] = b.w;
        __syncthreads();
#pragma unroll
        for (int k = 0; k < 32; ++k) {
            float a0 = As[k][ty * 2], a1 = As[k][ty * 2 + 1];
            float b0 = Bs[k][tx * 2], b1 = Bs[k][tx * 2 + 1];
            acc00 += a0 * b0; acc01 += a0 * b1;
            acc10 += a1 * b0; acc11 += a1 * b1;
        }
    }
    float bb0 = bias ? bias[n0 + tx * 2] : 0.f;
    float bb1 = bias ? bias[n0 + tx * 2 + 1] : 0.f;
    C[(m0 + ty * 2 + 0) * N + n0 + tx * 2 + 0] = acc00 + bb0;
    C[(m0 + ty * 2 + 0) * N + n0 + tx * 2 + 1] = acc01 + bb1;
    C[(m0 + ty * 2 + 1) * N + n0 + tx * 2 + 0] = acc10 + bb0;
    C[(m0 + ty * 2 + 1) * N + n0 + tx * 2 + 1] = acc11 + bb1;
}

// At[m][p] = sum_n WkT[m][n]*WqT[p][n]  (grid 16x16)
__global__ __launch_bounds__(256) void k_gemm_At() {
    gemm32_core(g_WkT, g_WqT, nullptr, g_At, HH, HH);
}

// q2[b][m] = sum_p h[b][p]*At[m][p] + bqk[m]  (grid 16x8)
__global__ __launch_bounds__(256) void k_gemm_q2(int par) {
    gemm32_core(g_hbuf[par], g_At, g_bqk, g_q2, HH, HH);
}

// ---------------- fused GEMM + LSTM cell ----------------
// gates[b][j] = sum_k X[b][k]*W[j][k] + add(b,j); then i,f,g,o -> (h,c) update.
// Block tile: 64 b x (16 h x 4 gate groups). Grid: (H/16=32, B/64=4). 256 threads.
template <int K, int MODE>   // MODE 0 = encoder, 1 = decoder
__global__ __launch_bounds__(256) void lstm_gemm_kernel(const float* __restrict__ Wenc,
                                                        const float* __restrict__ enc_inputs,
                                                        int par, int s) {
    __shared__ float As[16][68];
    __shared__ float Ws[16][68];
    const float* __restrict__ Wp = (MODE == 0) ? Wenc : g_Wdec;
    const float* __restrict__ Xh = g_hbuf[par];
    float* __restrict__ Hout = g_hbuf[par ^ 1];

    int tid = threadIdx.x;
    int h0 = blockIdx.x * 16;
    int b0 = blockIdx.y * 64;
    int ty = tid >> 4, tx = tid & 15;
    int lr = tid >> 2;            // 0..63
    int lk = (tid & 3) << 2;      // 0,4,8,12
    int gw = lr >> 4, hl = lr & 15;
    int jrow = gw * HH + h0 + hl; // W row for this loader thread

    float acc[4][4];
#pragma unroll
    for (int i = 0; i < 4; ++i)
#pragma unroll
        for (int g = 0; g < 4; ++g) acc[i][g] = 0.f;

    for (int kk = 0; kk < K; kk += 16) {
        int kg = kk + lk;
        float4 av;
        if (MODE == 0) {
            av = *(const float4*)(Xh + (b0 + lr) * HH + kg);
        } else {
            const float* src = (kg < HH) ? (Xh + (b0 + lr) * HH + kg)
                                         : (g_ctx + (b0 + lr) * HH + (kg - HH));
            av = *(const float4*)src;
        }
        float4 wv = *(const float4*)(Wp + (size_t)jrow * K + kg);
        __syncthreads();
        As[lk + 0][lr] = av.x; As[lk + 1][lr] = av.y; As[lk + 2][lr] = av.z; As[lk + 3][lr] = av.w;
        Ws[lk + 0][lr] = wv.x; Ws[lk + 1][lr] = wv.y; Ws[lk + 2][lr] = wv.z; Ws[lk + 3][lr] = wv.w;
        __syncthreads();
#pragma unroll
        for (int k = 0; k < 16; ++k) {
            float4 a = *(const float4*)(&As[k][ty * 4]);
            float w0 = Ws[k][tx];
            float w1 = Ws[k][tx + 16];
            float w2 = Ws[k][tx + 32];
            float w3 = Ws[k][tx + 48];
            acc[0][0] += a.x * w0; acc[1][0] += a.y * w0; acc[2][0] += a.z * w0; acc[3][0] += a.w * w0;
            acc[0][1] += a.x * w1; acc[1][1] += a.y * w1; acc[2][1] += a.z * w1; acc[3][1] += a.w * w1;
            acc[0][2] += a.x * w2; acc[1][2] += a.y * w2; acc[2][2] += a.z * w2; acc[3][2] += a.w * w2;
            acc[0][3] += a.x * w3; acc[1][3] += a.y * w3; acc[2][3] += a.z * w3; acc[3][3] += a.w * w3;
        }
    }

    int h = h0 + tx;
    float add0[4], add1[4];
#pragma unroll
    for (int g = 0; g < 4; ++g) {
        if (MODE == 0) { add0[g] = g_v[g * HH + h]; add1[g] = g_u[g * HH + h]; }
        else           { add0[g] = 0.f;             add1[g] = g_bd[g * HH + h]; }
    }
#pragma unroll
    for (int i = 0; i < 4; ++i) {
        int b = b0 + ty * 4 + i;
        float e = (MODE == 0) ? enc_inputs[b * SS + s] : 0.f;
        float r0 = acc[i][0] + e * add0[0] + add1[0];
        float r1 = acc[i][1] + e * add0[1] + add1[1];
        float r2 = acc[i][2] + e * add0[2] + add1[2];
        float r3 = acc[i][3] + e * add0[3] + add1[3];
        float ig = 1.f / (1.f + expf(-r0));
        float fg = 1.f / (1.f + expf(-r1));
        float gg = tanhf(r2);
        float og = 1.f / (1.f + expf(-r3));
        int idx = b * HH + h;
        float cn = fg * g_c[idx] + ig * gg;
        float hn = og * tanhf(cn);
        g_c[idx] = cn;
        Hout[idx] = hn;
        if (MODE == 0) g_hs[((size_t)s * BB + b) * HH + h] = hn;
    }
}

// ---------------- one-pass online-softmax attention ----------------
// Per block b: score_s = q2[b]·hs[s,b,:]; ctx[b] = softmax(score)·hs[:,b,:]
__global__ __launch_bounds__(256) void k_attn() {
    int b = blockIdx.x;
    int tid = threadIdx.x;
    int w = tid >> 5, ln = tid & 31;

    const float4* q4 = (const float4*)(g_q2 + b * HH + ln * 16);
    float4 q0 = q4[0], q1 = q4[1], q2v = q4[2], q3 = q4[3];

    float m = -INFINITY, l = 0.f;
    float ca[16];
#pragma unroll
    for (int q = 0; q < 16; ++q) ca[q] = 0.f;

    for (int it = 0; it < SS / 8; ++it) {
        int s = w + (it << 3);
        const float4* r4 = (const float4*)(g_hs + ((size_t)s * BB + b) * HH + ln * 16);
        float4 r0 = r4[0], r1 = r4[1], r2 = r4[2], r3 = r4[3];
        float dot = r0.x * q0.x + r0.y * q0.y + r0.z * q0.z + r0.w * q0.w
                  + r1.x * q1.x + r1.y * q1.y + r1.z * q1.z + r1.w * q1.w
                  + r2.x * q2v.x + r2.y * q2v.y + r2.z * q2v.z + r2.w * q2v.w
                  + r3.x * q3.x + r3.y * q3.y + r3.z * q3.z + r3.w * q3.w;
#pragma unroll
        for (int off = 16; off; off >>= 1) dot += __shfl_xor_sync(0xffffffffu, dot, off);
        float mn = fmaxf(m, dot);
        float scl = __expf(m - mn);
        float p = __expf(dot - mn);
        m = mn;
        l = l * scl + p;
        float rr[16] = {r0.x, r0.y, r0.z, r0.w, r1.x, r1.y, r1.z, r1.w,
                        r2.x, r2.y, r2.z, r2.w, r3.x, r3.y, r3.z, r3.w};
#pragma unroll
        for (int q = 0; q < 16; ++q) ca[q] = ca[q] * scl + p * rr[q];
    }

    __shared__ float sm[8], sl[8];
    __shared__ float sc[8][HH];
#pragma unroll
    for (int q = 0; q < 16; ++q) sc[w][ln * 16 + q] = ca[q];
    if (ln == 0) { sm[w] = m; sl[w] = l; }
    __syncthreads();

    float M = sm[0];
#pragma unroll
    for (int w2 = 1; w2 < 8; ++w2) M = fmaxf(M, sm[w2]);
    float ew[8];
    float L = 0.f;
#pragma unroll
    for (int w2 = 0; w2 < 8; ++w2) { ew[w2] = __expf(sm[w2] - M); L += sl[w2] * ew[w2]; }
    float invL = 1.f / L;
    for (int h = tid; h < HH; h += 256) {
        float v = 0.f;
#pragma unroll
        for (int w2 = 0; w2 < 8; ++w2) v += ew[w2] * sc[w2][h];
        g_ctx[b * HH + h] = v * invL;
    }
}

// ---------------- output projection: out[b][t] = h_new[b]·out_W + out_b ----------------
__global__ void k_out(int par, const float* __restrict__ outW, const float* __restrict__ outb,
                      float* __restrict__ out, int t) {
    int tid = threadIdx.x;
    int b = blockIdx.x * 8 + (tid >> 5);
    int ln = tid & 31;
    const float* hp = g_hbuf[par] + b * HH;
    float p = 0.f;
#pragma unroll
    for (int q = 0; q < 16; ++q) p += hp[ln + (q << 5)] * outW[ln + (q << 5)];
#pragma unroll
    for (int off = 16; off; off >>= 1) p += __shfl_xor_sync(0xffffffffu, p, off);
    if (ln == 0) out[b * TT + t] = p + outb[0];
}

// ---------------- host launcher ----------------
extern "C" void kernel_launch(void* const* d_in, const int* in_sizes, int n_in,
                              void* d_out, int out_size) {
    // input 1 may be the scalar out_seq_len; skip it if present (size 1)
    int off = (n_in >= 18 && in_sizes[1] == 1) ? 1 : 0;
    const float* enc_inputs = (const float*)d_in[0];
    const float* embed_W = (const float*)d_in[1 + off];
    const float* embed_b = (const float*)d_in[2 + off];
    const float* enc_Wih = (const float*)d_in[3 + off];
    const float* enc_Whh = (const float*)d_in[4 + off];
    const float* enc_bih = (const float*)d_in[5 + off];
    const float* enc_bhh = (const float*)d_in[6 + off];
    const float* dec_Wih = (const float*)d_in[7 + off];
    const float* dec_Whh = (const float*)d_in[8 + off];
    const float* dec_bih = (const float*)d_in[9 + off];
    const float* dec_bhh = (const float*)d_in[10 + off];
    const float* Wq = (const float*)d_in[11 + off];
    const float* bq = (const float*)d_in[12 + off];
    const float* Wk = (const float*)d_in[13 + off];
    // const float* bk = (const float*)d_in[14 + off];  // uniform shift over s: softmax-invariant, dropped
    const float* out_W = (const float*)d_in[15 + off];
    const float* out_b = (const float*)d_in[16 + off];
    float* out = (float*)d_out;

    float* g_WkT_p; cudaGetSymbolAddress((void**)&g_WkT_p, g_WkT);
    float* g_WqT_p; cudaGetSymbolAddress((void**)&g_WqT_p, g_WqT);

    // ---- prep ----
    k_zero<<<(BB * HH + 255) / 256, 256>>>();
    k_vu<<<GG / 256, 256>>>(embed_W, embed_b, enc_Wih, enc_bih, enc_bhh);
    k_wdec<<<(GG * K2) / 256, 256>>>(dec_Wih, dec_Whh, dec_bih, dec_bhh);
    k_bqk<<<HH / 256, 256>>>(bq, Wk);
    dim3 tb(32, 8);
    k_transpose512<<<dim3(16, 16), tb>>>(Wk, g_WkT_p);
    k_transpose512<<<dim3(16, 16), tb>>>(Wq, g_WqT_p);
    k_gemm_At<<<dim3(16, 16), 256>>>();

    // ---- encoder: 512 recurrent steps ----
    dim3 lgrid(HH / 16, BB / 64);  // 32 x 4
    for (int s = 0; s < SS; ++s)
        lstm_gemm_kernel<HH, 0><<<lgrid, 256>>>(enc_Whh, enc_inputs, s & 1, s);

    // ---- decoder: 96 steps ----
    for (int t = 0; t < TT; ++t) {
        int par = t & 1;
        k_gemm_q2<<<dim3(HH / 32, BB / 32), 256>>>(par);   // q2 = h@At + bqk
        k_attn<<<BB, 256>>>();                             // ctx from one-pass softmax over hs
        lstm_gemm_kernel<K2, 1><<<lgrid, 256>>>(nullptr, nullptr, par, 0);
        k_out<<<BB / 8, 256>>>(par ^ 1, out_W, out_b, out, t);
    }
    (void)in_sizes; (void)n_in; (void)out_size;
}

// round 2
// speedup vs baseline: 1.0040x; 1.0040x over previous
#include <cuda_runtime.h>
#include <math.h>

#define BB 256
#define SS 512
#define RR 128
#define HH 512
#define TT 96
#define GG 2048   // 4*H
#define K2 1024   // 2*H

// ---------------- device scratch (allocation-free: module globals) ----------------
__device__ float g_hs[SS * BB * HH];        // encoder hidden states [s][b][h] (256 MB)
__device__ float g_hbuf[2][BB * HH];        // ping-pong hidden state
__device__ float g_c[BB * HH];              // cell state (thread-owned, in-place)
__device__ float g_v[GG], g_u[GG], g_bd[GG];
__device__ float g_Wdec[GG * K2];           // combined decoder weight [j][k]
__device__ float g_WkT[HH * HH], g_WqT[HH * HH], g_At[HH * HH];
__device__ float g_bqk[HH];
__device__ float g_q2[BB * HH];
__device__ float g_ctx[BB * HH];

// ---------------- prep kernels ----------------
__global__ void k_zero() {
    int idx = blockIdx.x * 256 + threadIdx.x;
    if (idx < BB * HH) { g_hbuf[0][idx] = 0.f; g_c[idx] = 0.f; }
}

// v[j] = sum_r embed_W[r]*Wih[j,r]; u[j] = sum_r embed_b[r]*Wih[j,r] + bih[j] + bhh[j]
__global__ void k_vu(const float* __restrict__ embW, const float* __restrict__ embb,
                     const float* __restrict__ Wih, const float* __restrict__ bih,
                     const float* __restrict__ bhh) {
    int j = blockIdx.x * 256 + threadIdx.x;
    if (j >= GG) return;
    float v = 0.f, u = 0.f;
    const float* wr = Wih + j * RR;
#pragma unroll 8
    for (int r = 0; r < RR; ++r) { v += embW[r] * wr[r]; u += embb[r] * wr[r]; }
    g_v[j] = v;
    g_u[j] = u + bih[j] + bhh[j];
}

// Wdec[j][k] = dec_Wih[j][k] + (k<H ? dec_Whh[j][k] : 0); bd = bih+bhh
__global__ void k_wdec(const float* __restrict__ dWih, const float* __restrict__ dWhh,
                       const float* __restrict__ dbih, const float* __restrict__ dbhh) {
    int idx = blockIdx.x * 256 + threadIdx.x;
    if (idx < GG * K2) {
        int j = idx >> 10, k = idx & (K2 - 1);
        float w = dWih[idx];
        if (k < HH) w += dWhh[j * HH + k];
        g_Wdec[idx] = w;
    }
    if (idx < GG) g_bd[idx] = dbih[idx] + dbhh[idx];
}

// bqk[m] = sum_n bq[n] * Wk[n,m]
__global__ void k_bqk(const float* __restrict__ bq, const float* __restrict__ Wk) {
    int m = blockIdx.x * 256 + threadIdx.x;
    if (m >= HH) return;
    float a = 0.f;
    for (int n = 0; n < HH; ++n) a += bq[n] * Wk[n * HH + m];
    g_bqk[m] = a;
}

// 512x512 transpose
__global__ void k_transpose512(const float* __restrict__ in, float* __restrict__ out) {
    __shared__ float t[32][33];
    int x = blockIdx.x * 32 + threadIdx.x;
    int y0 = blockIdx.y * 32;
    for (int j = threadIdx.y; j < 32; j += 8) t[j][threadIdx.x] = in[(y0 + j) * HH + x];
    __syncthreads();
    int x2 = y0 + threadIdx.x;
    int y20 = blockIdx.x * 32;
    for (int j = threadIdx.y; j < 32; j += 8) out[(y20 + j) * HH + x2] = t[threadIdx.x][j];
}

// ---------------- generic 32x32-tile fp32 GEMM core: C[m][n] = sum_k A[m][k]*Bw[n][k] (+bias[n]) ----------------
__device__ __forceinline__ void gemm32_core(const float* __restrict__ A,
                                            const float* __restrict__ Bw,
                                            const float* __restrict__ bias,
                                            float* __restrict__ C, int N, int K) {
    __shared__ float As[32][33];
    __shared__ float Bs[32][33];
    int tid = threadIdx.x;
    int m0 = blockIdx.y * 32, n0 = blockIdx.x * 32;
    int lr = tid >> 3, lk = (tid & 7) << 2;
    int ty = tid >> 4, tx = tid & 15;
    float acc00 = 0.f, acc01 = 0.f, acc10 = 0.f, acc11 = 0.f;
    for (int kk = 0; kk < K; kk += 32) {
        float4 a = *(const float4*)(A + (m0 + lr) * K + kk + lk);
        float4 b = *(const float4*)(Bw + (n0 + lr) * K + kk + lk);
        __syncthreads();
        As[lk + 0][lr] = a.x; As[lk + 1][lr] = a.y; As[lk + 2][lr] = a.z; As[lk + 3][lr] = a.w;
        Bs[lk + 0][lr] = b.x; Bs[lk + 1][lr] = b.y; Bs[lk + 2][lr] = b.z; Bs[lk + 3][lr] = b.w;
        __syncthreads();
#pragma unroll
        for (int k = 0; k < 32; ++k) {
            float a0 = As[k][ty * 2], a1 = As[k][ty * 2 + 1];
            float b0 = Bs[k][tx * 2], b1 = Bs[k][tx * 2 + 1];
            acc00 += a0 * b0; acc01 += a0 * b1;
            acc10 += a1 * b0; acc11 += a1 * b1;
        }
    }
    float bb0 = bias ? bias[n0 + tx * 2] : 0.f;
    float bb1 = bias ? bias[n0 + tx * 2 + 1] : 0.f;
    C[(m0 + ty * 2 + 0) * N + n0 + tx * 2 + 0] = acc00 + bb0;
    C[(m0 + ty * 2 + 0) * N + n0 + tx * 2 + 1] = acc01 + bb1;
    C[(m0 + ty * 2 + 1) * N + n0 + tx * 2 + 0] = acc10 + bb0;
    C[(m0 + ty * 2 + 1) * N + n0 + tx * 2 + 1] = acc11 + bb1;
}

// At[m][p] = sum_n WkT[m][n]*WqT[p][n]  (grid 16x16)
__global__ __launch_bounds__(256) void k_gemm_At() {
    gemm32_core(g_WkT, g_WqT, nullptr, g_At, HH, HH);
}

// q2[b][m] = sum_p h[b][p]*At[m][p] + bqk[m]  (grid 16x8)
__global__ __launch_bounds__(256) void k_gemm_q2(int par) {
    gemm32_core(g_hbuf[par], g_At, g_bqk, g_q2, HH, HH);
}

// ---------------- fused GEMM + LSTM cell ----------------
// gates[b][j] = sum_k X[b][k]*W[j][k] + add(b,j); then i,f,g,o -> (h,c) update.
// Block tile: 64 b x (16 h x 4 gate groups). Grid: (H/16=32, B/64=4). 256 threads.
template <int K, int MODE>   // MODE 0 = encoder, 1 = decoder
__global__ __launch_bounds__(256) void lstm_gemm_kernel(const float* __restrict__ Wenc,
                                                        const float* __restrict__ enc_inputs,
                                                        int par, int s) {
    __shared__ float As[16][68];
    __shared__ float Ws[16][68];
    const float* __restrict__ Wp = (MODE == 0) ? Wenc : g_Wdec;
    const float* __restrict__ Xh = g_hbuf[par];
    float* __restrict__ Hout = g_hbuf[par ^ 1];

    int tid = threadIdx.x;
    int h0 = blockIdx.x * 16;
    int b0 = blockIdx.y * 64;
    int ty = tid >> 4, tx = tid & 15;
    int lr = tid >> 2;            // 0..63
    int lk = (tid & 3) << 2;      // 0,4,8,12
    int gw = lr >> 4, hl = lr & 15;
    int jrow = gw * HH + h0 + hl; // W row for this loader thread

    float acc[4][4];
#pragma unroll
    for (int i = 0; i < 4; ++i)
#pragma unroll
        for (int g = 0; g < 4; ++g) acc[i][g] = 0.f;

    for (int kk = 0; kk < K; kk += 16) {
        int kg = kk + lk;
        float4 av;
        if (MODE == 0) {
            av = *(const float4*)(Xh + (b0 + lr) * HH + kg);
        } else {
            const float* src = (kg < HH) ? (Xh + (b0 + lr) * HH + kg)
                                         : (g_ctx + (b0 + lr) * HH + (kg - HH));
            av = *(const float4*)src;
        }
        float4 wv = *(const float4*)(Wp + (size_t)jrow * K + kg);
        __syncthreads();
        As[lk + 0][lr] = av.x; As[lk + 1][lr] = av.y; As[lk + 2][lr] = av.z; As[lk + 3][lr] = av.w;
        Ws[lk + 0][lr] = wv.x; Ws[lk + 1][lr] = wv.y; Ws[lk + 2][lr] = wv.z; Ws[lk + 3][lr] = wv.w;
        __syncthreads();
#pragma unroll
        for (int k = 0; k < 16; ++k) {
            float4 a = *(const float4*)(&As[k][ty * 4]);
            float w0 = Ws[k][tx];
            float w1 = Ws[k][tx + 16];
            float w2 = Ws[k][tx + 32];
            float w3 = Ws[k][tx + 48];
            acc[0][0] += a.x * w0; acc[1][0] += a.y * w0; acc[2][0] += a.z * w0; acc[3][0] += a.w * w0;
            acc[0][1] += a.x * w1; acc[1][1] += a.y * w1; acc[2][1] += a.z * w1; acc[3][1] += a.w * w1;
            acc[0][2] += a.x * w2; acc[1][2] += a.y * w2; acc[2][2] += a.z * w2; acc[3][2] += a.w * w2;
            acc[0][3] += a.x * w3; acc[1][3] += a.y * w3; acc[2][3] += a.z * w3; acc[3][3] += a.w * w3;
        }
    }

    int h = h0 + tx;
    float add0[4], add1[4];
#pragma unroll
    for (int g = 0; g < 4; ++g) {
        if (MODE == 0) { add0[g] = g_v[g * HH + h]; add1[g] = g_u[g * HH + h]; }
        else           { add0[g] = 0.f;             add1[g] = g_bd[g * HH + h]; }
    }
#pragma unroll
    for (int i = 0; i < 4; ++i) {
        int b = b0 + ty * 4 + i;
        float e = (MODE == 0) ? enc_inputs[b * SS + s] : 0.f;
        float r0 = acc[i][0] + e * add0[0] + add1[0];
        float r1 = acc[i][1] + e * add0[1] + add1[1];
        float r2 = acc[i][2] + e * add0[2] + add1[2];
        float r3 = acc[i][3] + e * add0[3] + add1[3];
        float ig = 1.f / (1.f + expf(-r0));
        float fg = 1.f / (1.f + expf(-r1));
        float gg = tanhf(r2);
        float og = 1.f / (1.f + expf(-r3));
        int idx = b * HH + h;
        float cn = fg * g_c[idx] + ig * gg;
        float hn = og * tanhf(cn);
        g_c[idx] = cn;
        Hout[idx] = hn;
        if (MODE == 0) g_hs[((size_t)s * BB + b) * HH + h] = hn;
    }
}

// ---------------- one-pass online-softmax attention ----------------
// Per block b: score_s = q2[b]·hs[s,b,:]; ctx[b] = softmax(score)·hs[:,b,:]
__global__ __launch_bounds__(256) void k_attn() {
    int b = blockIdx.x;
    int tid = threadIdx.x;
    int w = tid >> 5, ln = tid & 31;

    const float4* q4 = (const float4*)(g_q2 + b * HH + ln * 16);
    float4 q0 = q4[0], q1 = q4[1], q2v = q4[2], q3 = q4[3];

    float m = -INFINITY, l = 0.f;
    float ca[16];
#pragma unroll
    for (int q = 0; q < 16; ++q) ca[q] = 0.f;

    for (int it = 0; it < SS / 8; ++it) {
        int s = w + (it << 3);
        const float4* r4 = (const float4*)(g_hs + ((size_t)s * BB + b) * HH + ln * 16);
        float4 r0 = r4[0], r1 = r4[1], r2 = r4[2], r3 = r4[3];
        float dot = r0.x * q0.x + r0.y * q0.y + r0.z * q0.z + r0.w * q0.w
                  + r1.x * q1.x + r1.y * q1.y + r1.z * q1.z + r1.w * q1.w
                  + r2.x * q2v.x + r2.y * q2v.y + r2.z * q2v.z + r2.w * q2v.w
                  + r3.x * q3.x + r3.y * q3.y + r3.z * q3.z + r3.w * q3.w;
#pragma unroll
        for (int off = 16; off; off >>= 1) dot += __shfl_xor_sync(0xffffffffu, dot, off);
        float mn = fmaxf(m, dot);
        float scl = __expf(m - mn);
        float p = __expf(dot - mn);
        m = mn;
        l = l * scl + p;
        float rr[16] = {r0.x, r0.y, r0.z, r0.w, r1.x, r1.y, r1.z, r1.w,
                        r2.x, r2.y, r2.z, r2.w, r3.x, r3.y, r3.z, r3.w};
#pragma unroll
        for (int q = 0; q < 16; ++q) ca[q] = ca[q] * scl + p * rr[q];
    }

    __shared__ float sm[8], sl[8];
    __shared__ float sc[8][HH];
#pragma unroll
    for (int q = 0; q < 16; ++q) sc[w][ln * 16 + q] = ca[q];
    if (ln == 0) { sm[w] = m; sl[w] = l; }
    __syncthreads();

    float M = sm[0];
#pragma unroll
    for (int w2 = 1; w2 < 8; ++w2) M = fmaxf(M, sm[w2]);
    float ew[8];
    float L = 0.f;
#pragma unroll
    for (int w2 = 0; w2 < 8; ++w2) { ew[w2] = __expf(sm[w2] - M); L += sl[w2] * ew[w2]; }
    float invL = 1.f / L;
    for (int h = tid; h < HH; h += 256) {
        float v = 0.f;
#pragma unroll
        for (int w2 = 0; w2 < 8; ++w2) v += ew[w2] * sc[w2][h];
        g_ctx[b * HH + h] = v * invL;
    }
}

// ---------------- output projection: out[b][t] = h_new[b]·out_W + out_b ----------------
__global__ void k_out(int par, const float* __restrict__ outW, const float* __restrict__ outb,
                      float* __restrict__ out, int t) {
    int tid = threadIdx.x;
    int b = blockIdx.x * 8 + (tid >> 5);
    int ln = tid & 31;
    const float* hp = g_hbuf[par] + b * HH;
    float p = 0.f;
#pragma unroll
    for (int q = 0; q < 16; ++q) p += hp[ln + (q << 5)] * outW[ln + (q << 5)];
#pragma unroll
    for (int off = 16; off; off >>= 1) p += __shfl_xor_sync(0xffffffffu, p, off);
    if (ln == 0) out[b * TT + t] = p + outb[0];
}

// ---------------- host launcher ----------------
extern "C" void kernel_launch(void* const* d_in, const int* in_sizes, int n_in,
                              void* d_out, int out_size) {
    // input 1 may be the scalar out_seq_len; skip it if present (size 1)
    int off = (n_in >= 18 && in_sizes[1] == 1) ? 1 : 0;
    const float* enc_inputs = (const float*)d_in[0];
    const float* embed_W = (const float*)d_in[1 + off];
    const float* embed_b = (const float*)d_in[2 + off];
    const float* enc_Wih = (const float*)d_in[3 + off];
    const float* enc_Whh = (const float*)d_in[4 + off];
    const float* enc_bih = (const float*)d_in[5 + off];
    const float* enc_bhh = (const float*)d_in[6 + off];
    const float* dec_Wih = (const float*)d_in[7 + off];
    const float* dec_Whh = (const float*)d_in[8 + off];
    const float* dec_bih = (const float*)d_in[9 + off];
    const float* dec_bhh = (const float*)d_in[10 + off];
    const float* Wq = (const float*)d_in[11 + off];
    const float* bq = (const float*)d_in[12 + off];
    const float* Wk = (const float*)d_in[13 + off];
    // const float* bk = (const float*)d_in[14 + off];  // uniform shift over s: softmax-invariant, dropped
    const float* out_W = (const float*)d_in[15 + off];
    const float* out_b = (const float*)d_in[16 + off];
    float* out = (float*)d_out;

    float* g_WkT_p; cudaGetSymbolAddress((void**)&g_WkT_p, g_WkT);
    float* g_WqT_p; cudaGetSymbolAddress((void**)&g_WqT_p, g_WqT);

    // ---- prep ----
    k_zero<<<(BB * HH + 255) / 256, 256>>>();
    k_vu<<<GG / 256, 256>>>(embed_W, embed_b, enc_Wih, enc_bih, enc_bhh);
    k_wdec<<<(GG * K2) / 256, 256>>>(dec_Wih, dec_Whh, dec_bih, dec_bhh);
    k_bqk<<<HH / 256, 256>>>(bq, Wk);
    dim3 tb(32, 8);
    k_transpose512<<<dim3(16, 16), tb>>>(Wk, g_WkT_p);
    k_transpose512<<<dim3(16, 16), tb>>>(Wq, g_WqT_p);
    k_gemm_At<<<dim3(16, 16), 256>>>();

    // ---- encoder: 512 recurrent steps ----
    dim3 lgrid(HH / 16, BB / 64);  // 32 x 4
    for (int s = 0; s < SS; ++s)
        lstm_gemm_kernel<HH, 0><<<lgrid, 256>>>(enc_Whh, enc_inputs, s & 1, s);

    // ---- decoder: 96 steps ----
    for (int t = 0; t < TT; ++t) {
        int par = t & 1;
        k_gemm_q2<<<dim3(HH / 32, BB / 32), 256>>>(par);   // q2 = h@At + bqk
        k_attn<<<BB, 256>>>();                             // ctx from one-pass softmax over hs
        lstm_gemm_kernel<K2, 1><<<lgrid, 256>>>(nullptr, nullptr, par, 0);
        k_out<<<BB / 8, 256>>>(par ^ 1, out_W, out_b, out, t);
    }
    (void)in_sizes; (void)n_in; (void)out_size;
}

// round 4
// speedup vs baseline: 1.4376x; 1.4318x over previous
#include <cuda_runtime.h>
#include <cuda_bf16.h>
#include <math.h>
#include <stdint.h>

#define BB 256
#define SS 512
#define RR 128
#define HH 512
#define TT 96
#define GG 2048   // 4*H
#define K2 1024   // 2*H

// ---------------- device scratch ----------------
__device__ float g_hs[(size_t)SS * BB * HH];        // encoder hidden states [s][b][h] fp32
__device__ float g_hbuf[2][BB * HH];                // ping-pong hidden (fp32, for q2/out)
__device__ float g_c[BB * HH];                      // cell state fp32
__device__ __nv_bfloat16 g_hhi[2][BB * HH], g_hlo[2][BB * HH];   // split-bf16 h ping-pong
__device__ __nv_bfloat16 g_ctxhi[BB * HH], g_ctxlo[BB * HH];     // split-bf16 context
__device__ __nv_bfloat16 g_Wenc_hi[GG * HH],  g_Wenc_lo[GG * HH];   // gate-interleaved enc Whh
__device__ __nv_bfloat16 g_Wdec_hi[GG * K2],  g_Wdec_lo[GG * K2];   // gate-interleaved dec (Wih+Whh)
__device__ float g_v2[GG], g_u2[GG], g_bd2[GG];     // gate-interleaved rank-1 input / biases
__device__ float g_WkT[HH * HH], g_WqT[HH * HH], g_At[HH * HH];
__device__ float g_bqk[HH];
__device__ float g_q2[BB * HH];

// ---------------- helpers ----------------
__device__ __forceinline__ uint32_t smem_u32(const void* p) {
    uint32_t a;
    asm("{ .reg .u64 t; cvta.to.shared.u64 t, %1; cvt.u32.u64 %0, t; }" : "=r"(a) : "l"(p));
    return a;
}
__device__ __forceinline__ void cp16(uint32_t dst, const void* src) {
    asm volatile("cp.async.cg.shared.global [%0], [%1], 16;" :: "r"(dst), "l"(src) : "memory");
}
#define CP_COMMIT() asm volatile("cp.async.commit_group;" ::: "memory")
#define CP_WAIT1()  asm volatile("cp.async.wait_group 1;" ::: "memory")

__device__ __forceinline__ void ldm4(uint32_t* r, uint32_t addr) {
    asm volatile("ldmatrix.sync.aligned.m8n8.x4.shared.b16 {%0,%1,%2,%3}, [%4];"
                 : "=r"(r[0]), "=r"(r[1]), "=r"(r[2]), "=r"(r[3]) : "r"(addr));
}
__device__ __forceinline__ void mma16816(float* c, const uint32_t* a, uint32_t b0, uint32_t b1) {
    asm volatile(
        "mma.sync.aligned.m16n8k16.row.col.f32.bf16.bf16.f32 "
        "{%0,%1,%2,%3}, {%4,%5,%6,%7}, {%8,%9}, {%0,%1,%2,%3};"
        : "+f"(c[0]), "+f"(c[1]), "+f"(c[2]), "+f"(c[3])
        : "r"(a[0]), "r"(a[1]), "r"(a[2]), "r"(a[3]), "r"(b0), "r"(b1));
}

// SMEM: 4 tiles of 64 rows x 144B (64 k-bf16 + pad), double buffered.
#define T_ROW   144
#define T_SZ    (64 * T_ROW)          // 9216
#define TA_HI   0
#define TA_LO   (1 * T_SZ)
#define TB_HI   (2 * T_SZ)
#define TB_LO   (3 * T_SZ)
#define BUFS    (4 * T_SZ)            // 36864
#define SMEM_BYTES (2 * BUFS)         // 73728

// ---------------- fused HMMA split-bf16 GEMM + LSTM cell ----------------
// gates[b][j'] = sum_k X[b][k]*W[j'][k]; j' = h*4+g.
// Grid (GG/64=32 n-tiles, BB/64=4 m-tiles), 256 threads (8 warps, warp tile m16 x n32).
template <int KDIM, int MODE>   // MODE 0 = encoder (X=h), 1 = decoder (X=[h|ctx])
__global__ __launch_bounds__(256) void lstm_mma(const float* __restrict__ enc_inputs, int par, int s) {
    constexpr int NCH = KDIM / 64;
    extern __shared__ char smem[];
    uint32_t sb = smem_u32(smem);

    int tid = threadIdx.x;
    int w = tid >> 5, l = tid & 31;
    int n0 = blockIdx.x * 64;
    int m0 = blockIdx.y * 64;
    int mrow = (w & 3) * 16;
    int ncol = (w >> 2) * 32;

    const __nv_bfloat16* __restrict__ Whi = (MODE == 0) ? g_Wenc_hi : g_Wdec_hi;
    const __nv_bfloat16* __restrict__ Wlo = (MODE == 0) ? g_Wenc_lo : g_Wdec_lo;

    float acc[4][4];
#pragma unroll
    for (int nt = 0; nt < 4; ++nt)
#pragma unroll
        for (int r = 0; r < 4; ++r) acc[nt][r] = 0.f;

    auto issue = [&](int c) {
        if (c < NCH) {
            int c0 = c * 64;
            const __nv_bfloat16 *ah, *al;
            int ac0;
            if (MODE == 1 && c0 >= HH) { ah = g_ctxhi; al = g_ctxlo; ac0 = c0 - HH; }
            else                        { ah = g_hhi[par]; al = g_hlo[par]; ac0 = c0; }
            uint32_t buf = sb + (c & 1) * BUFS;
#pragma unroll
            for (int i = 0; i < 2; ++i) {
                int e = tid + i * 256;       // 0..511
                int r = e >> 3, cu = e & 7;  // row, 16B unit
                uint32_t d = buf + r * T_ROW + cu * 16;
                cp16(d + TA_HI, ah + (m0 + r) * HH + ac0 + cu * 8);
                cp16(d + TA_LO, al + (m0 + r) * HH + ac0 + cu * 8);
                cp16(d + TB_HI, Whi + (size_t)(n0 + r) * KDIM + c0 + cu * 8);
                cp16(d + TB_LO, Wlo + (size_t)(n0 + r) * KDIM + c0 + cu * 8);
            }
        }
        CP_COMMIT();
    };

    issue(0);
    for (int c = 0; c < NCH; ++c) {
        issue(c + 1);
        CP_WAIT1();
        __syncthreads();
        uint32_t base = sb + (c & 1) * BUFS;
        uint32_t rowsel = (l & 15) * T_ROW + (l >> 4) * 16;
#pragma unroll
        for (int kk = 0; kk < 4; ++kk) {   // four k16 steps
            uint32_t kof = kk * 32;        // 2 x 16B units per k16
            uint32_t aaddr = base + TA_HI + mrow * T_ROW + rowsel + kof;
            uint32_t baddr = base + TB_HI + ncol * T_ROW + rowsel + kof;
            uint32_t ah[4], al[4], bh[8], bl[8];
            ldm4(ah, aaddr);
            ldm4(al, aaddr + (TA_LO - TA_HI));
            ldm4(bh, baddr);
            ldm4(bh + 4, baddr + 16 * T_ROW);
            ldm4(bl, baddr + (TB_LO - TB_HI));
            ldm4(bl + 4, baddr + (TB_LO - TB_HI) + 16 * T_ROW);
#pragma unroll
            for (int nt = 0; nt < 4; ++nt) {
                uint32_t b0h = bh[(nt & 1) + (nt >> 1) * 4];
                uint32_t b1h = bh[(nt & 1) + (nt >> 1) * 4 + 2];
                uint32_t b0l = bl[(nt & 1) + (nt >> 1) * 4];
                uint32_t b1l = bl[(nt & 1) + (nt >> 1) * 4 + 2];
                mma16816(acc[nt], ah, b0h, b1h);
                mma16816(acc[nt], al, b0h, b1h);
                mma16816(acc[nt], ah, b0l, b1l);
            }
        }
        __syncthreads();
    }

    // ---- epilogue: accums -> smem (reuse tile buffers), then LSTM cell ----
    float* Cs = (float*)smem;   // 64 x 68 fp32
    {
        int g = l >> 2, cc = l & 3;
#pragma unroll
        for (int nt = 0; nt < 4; ++nt) {
            int col = ncol + nt * 8 + cc * 2;
            int r0 = mrow + g, r1 = mrow + g + 8;
            Cs[r0 * 68 + col]     = acc[nt][0];
            Cs[r0 * 68 + col + 1] = acc[nt][1];
            Cs[r1 * 68 + col]     = acc[nt][2];
            Cs[r1 * 68 + col + 1] = acc[nt][3];
        }
    }
    __syncthreads();

    int bl_ = tid & 63;
    int q0 = (tid >> 6) * 4;       // 4 h's per thread
    int b = m0 + bl_;
    int hbase = n0 >> 2;
    int op = par ^ 1;
    float e = (MODE == 0) ? enc_inputs[b * SS + s] : 0.f;
#pragma unroll
    for (int q = 0; q < 4; ++q) {
        int hl = q0 + q;
        int jl = hl * 4;
        int jp = n0 + jl;
        float ri, rf, rg, ro;
        if (MODE == 0) {
            ri = Cs[bl_ * 68 + jl + 0] + e * g_v2[jp + 0] + g_u2[jp + 0];
            rf = Cs[bl_ * 68 + jl + 1] + e * g_v2[jp + 1] + g_u2[jp + 1];
            rg = Cs[bl_ * 68 + jl + 2] + e * g_v2[jp + 2] + g_u2[jp + 2];
            ro = Cs[bl_ * 68 + jl + 3] + e * g_v2[jp + 3] + g_u2[jp + 3];
        } else {
            ri = Cs[bl_ * 68 + jl + 0] + g_bd2[jp + 0];
            rf = Cs[bl_ * 68 + jl + 1] + g_bd2[jp + 1];
            rg = Cs[bl_ * 68 + jl + 2] + g_bd2[jp + 2];
            ro = Cs[bl_ * 68 + jl + 3] + g_bd2[jp + 3];
        }
        float ig = 1.f / (1.f + expf(-ri));
        float fg = 1.f / (1.f + expf(-rf));
        float gg = tanhf(rg);
        float og = 1.f / (1.f + expf(-ro));
        int idx = b * HH + hbase + hl;
        float cn = fg * g_c[idx] + ig * gg;
        float hn = og * tanhf(cn);
        g_c[idx] = cn;
        g_hbuf[op][idx] = hn;
        __nv_bfloat16 hi = __float2bfloat16(hn);
        g_hhi[op][idx] = hi;
        g_hlo[op][idx] = __float2bfloat16(hn - __bfloat162float(hi));
        if (MODE == 0) g_hs[((size_t)s * BB + b) * HH + hbase + hl] = hn;
    }
}

// ---------------- prep kernels ----------------
__global__ void k_zero() {
    int idx = blockIdx.x * 256 + threadIdx.x;
    if (idx < BB * HH) {
        g_c[idx] = 0.f;
        g_hhi[0][idx] = __float2bfloat16(0.f);
        g_hlo[0][idx] = __float2bfloat16(0.f);
    }
}

__global__ void k_vu(const float* __restrict__ embW, const float* __restrict__ embb,
                     const float* __restrict__ Wih, const float* __restrict__ bih,
                     const float* __restrict__ bhh) {
    int j = blockIdx.x * 256 + threadIdx.x;
    if (j >= GG) return;
    float v = 0.f, u = 0.f;
    const float* wr = Wih + j * RR;
#pragma unroll 8
    for (int r = 0; r < RR; ++r) { v += embW[r] * wr[r]; u += embb[r] * wr[r]; }
    int jp = ((j & (HH - 1)) << 2) | (j >> 9);   // j = g*H+h -> j' = h*4+g
    g_v2[jp] = v;
    g_u2[jp] = u + bih[j] + bhh[j];
}

__global__ void k_wenc_split(const float* __restrict__ Whh) {
    int idx = blockIdx.x * 256 + threadIdx.x;
    if (idx >= GG * HH) return;
    int jp = idx >> 9, k = idx & (HH - 1);
    int h = jp >> 2, g = jp & 3;
    float w = Whh[(g * HH + h) * HH + k];
    __nv_bfloat16 hi = __float2bfloat16(w);
    g_Wenc_hi[idx] = hi;
    g_Wenc_lo[idx] = __float2bfloat16(w - __bfloat162float(hi));
}

__global__ void k_wdec_split(const float* __restrict__ dWih, const float* __restrict__ dWhh,
                             const float* __restrict__ dbih, const float* __restrict__ dbhh) {
    int idx = blockIdx.x * 256 + threadIdx.x;
    if (idx < GG * K2) {
        int jp = idx >> 10, k = idx & (K2 - 1);
        int h = jp >> 2, g = jp & 3;
        float w = dWih[(g * HH + h) * K2 + k];
        if (k < HH) w += dWhh[(g * HH + h) * HH + k];
        __nv_bfloat16 hi = __float2bfloat16(w);
        g_Wdec_hi[idx] = hi;
        g_Wdec_lo[idx] = __float2bfloat16(w - __bfloat162float(hi));
    }
    if (idx < GG) {
        int h = idx >> 2, g = idx & 3;
        g_bd2[idx] = dbih[g * HH + h] + dbhh[g * HH + h];
    }
}

__global__ void k_bqk(const float* __restrict__ bq, const float* __restrict__ Wk) {
    int m = blockIdx.x * 256 + threadIdx.x;
    if (m >= HH) return;
    float a = 0.f;
    for (int n = 0; n < HH; ++n) a += bq[n] * Wk[n * HH + m];
    g_bqk[m] = a;
}

__global__ void k_transpose512(const float* __restrict__ in, float* __restrict__ out) {
    __shared__ float t[32][33];
    int x = blockIdx.x * 32 + threadIdx.x;
    int y0 = blockIdx.y * 32;
    for (int j = threadIdx.y; j < 32; j += 8) t[j][threadIdx.x] = in[(y0 + j) * HH + x];
    __syncthreads();
    int x2 = y0 + threadIdx.x;
    int y20 = blockIdx.x * 32;
    for (int j = threadIdx.y; j < 32; j += 8) out[(y20 + j) * HH + x2] = t[threadIdx.x][j];
}

// ---------------- 32x32-tile fp32 GEMM: C[m][n] = sum_k A[m][k]*Bw[n][k] (+bias[n]) ----------------
__device__ __forceinline__ void gemm32_core(const float* __restrict__ A,
                                            const float* __restrict__ Bw,
                                            const float* __restrict__ bias,
                                            float* __restrict__ C, int N, int K) {
    __shared__ float As[32][33];
    __shared__ float Bs[32][33];
    int tid = threadIdx.x;
    int m0 = blockIdx.y * 32, n0 = blockIdx.x * 32;
    int lr = tid >> 3, lk = (tid & 7) << 2;
    int ty = tid >> 4, tx = tid & 15;
    float acc00 = 0.f, acc01 = 0.f, acc10 = 0.f, acc11 = 0.f;
    for (int kk = 0; kk < K; kk += 32) {
        float4 a = *(const float4*)(A + (m0 + lr) * K + kk + lk);
        float4 b = *(const float4*)(Bw + (n0 + lr) * K + kk + lk);
        __syncthreads();
        As[lk + 0][lr] = a.x; As[lk + 1][lr] = a.y; As[lk + 2][lr] = a.z; As[lk + 3][lr] = a.w;
        Bs[lk + 0][lr] = b.x; Bs[lk + 1][lr] = b.y; Bs[lk + 2][lr] = b.z; Bs[lk + 3][lr] = b.w;
        __syncthreads();
#pragma unroll
        for (int k = 0; k < 32; ++k) {
            float a0 = As[k][ty * 2], a1 = As[k][ty * 2 + 1];
            float b0 = Bs[k][tx * 2], b1 = Bs[k][tx * 2 + 1];
            acc00 += a0 * b0; acc01 += a0 * b1;
            acc10 += a1 * b0; acc11 += a1 * b1;
        }
    }
    float bb0 = bias ? bias[n0 + tx * 2] : 0.f;
    float bb1 = bias ? bias[n0 + tx * 2 + 1] : 0.f;
    C[(m0 + ty * 2 + 0) * N + n0 + tx * 2 + 0] = acc00 + bb0;
    C[(m0 + ty * 2 + 0) * N + n0 + tx * 2 + 1] = acc01 + bb1;
    C[(m0 + ty * 2 + 1) * N + n0 + tx * 2 + 0] = acc10 + bb0;
    C[(m0 + ty * 2 + 1) * N + n0 + tx * 2 + 1] = acc11 + bb1;
}

__global__ __launch_bounds__(256) void k_gemm_At() {
    gemm32_core(g_WkT, g_WqT, nullptr, g_At, HH, HH);
}
__global__ __launch_bounds__(256) void k_gemm_q2(int par) {
    gemm32_core(g_hbuf[par], g_At, g_bqk, g_q2, HH, HH);
}

// ---------------- one-pass online-softmax attention ----------------
__global__ __launch_bounds__(256) void k_attn() {
    int b = blockIdx.x;
    int tid = threadIdx.x;
    int w = tid >> 5, ln = tid & 31;

    const float4* q4 = (const float4*)(g_q2 + b * HH + ln * 16);
    float4 q0 = q4[0], q1 = q4[1], q2v = q4[2], q3 = q4[3];

    float m = -INFINITY, l = 0.f;
    float ca[16];
#pragma unroll
    for (int q = 0; q < 16; ++q) ca[q] = 0.f;

    for (int it = 0; it < SS / 8; ++it) {
        int s = w + (it << 3);
        const float4* r4 = (const float4*)(g_hs + ((size_t)s * BB + b) * HH + ln * 16);
        float4 r0 = r4[0], r1 = r4[1], r2 = r4[2], r3 = r4[3];
        float dot = r0.x * q0.x + r0.y * q0.y + r0.z * q0.z + r0.w * q0.w
                  + r1.x * q1.x + r1.y * q1.y + r1.z * q1.z + r1.w * q1.w
                  + r2.x * q2v.x + r2.y * q2v.y + r2.z * q2v.z + r2.w * q2v.w
                  + r3.x * q3.x + r3.y * q3.y + r3.z * q3.z + r3.w * q3.w;
#pragma unroll
        for (int off = 16; off; off >>= 1) dot += __shfl_xor_sync(0xffffffffu, dot, off);
        float mn = fmaxf(m, dot);
        float scl = __expf(m - mn);
        float p = __expf(dot - mn);
        m = mn;
        l = l * scl + p;
        float rr[16] = {r0.x, r0.y, r0.z, r0.w, r1.x, r1.y, r1.z, r1.w,
                        r2.x, r2.y, r2.z, r2.w, r3.x, r3.y, r3.z, r3.w};
#pragma unroll
        for (int q = 0; q < 16; ++q) ca[q] = ca[q] * scl + p * rr[q];
    }

    __shared__ float sm[8], sl[8];
    __shared__ float sc[8][HH];
#pragma unroll
    for (int q = 0; q < 16; ++q) sc[w][ln * 16 + q] = ca[q];
    if (ln == 0) { sm[w] = m; sl[w] = l; }
    __syncthreads();

    float M = sm[0];
#pragma unroll
    for (int w2 = 1; w2 < 8; ++w2) M = fmaxf(M, sm[w2]);
    float ew[8];
    float L = 0.f;
#pragma unroll
    for (int w2 = 0; w2 < 8; ++w2) { ew[w2] = __expf(sm[w2] - M); L += sl[w2] * ew[w2]; }
    float invL = 1.f / L;
    for (int h = tid; h < HH; h += 256) {
        float v = 0.f;
#pragma unroll
        for (int w2 = 0; w2 < 8; ++w2) v += ew[w2] * sc[w2][h];
        v *= invL;
        __nv_bfloat16 hi = __float2bfloat16(v);
        g_ctxhi[b * HH + h] = hi;
        g_ctxlo[b * HH + h] = __float2bfloat16(v - __bfloat162float(hi));
    }
}

// ---------------- output projection ----------------
__global__ void k_out(int par, const float* __restrict__ outW, const float* __restrict__ outb,
                      float* __restrict__ out, int t) {
    int tid = threadIdx.x;
    int b = blockIdx.x * 8 + (tid >> 5);
    int ln = tid & 31;
    const float* hp = g_hbuf[par] + b * HH;
    float p = 0.f;
#pragma unroll
    for (int q = 0; q < 16; ++q) p += hp[ln + (q << 5)] * outW[ln + (q << 5)];
#pragma unroll
    for (int off = 16; off; off >>= 1) p += __shfl_xor_sync(0xffffffffu, p, off);
    if (ln == 0) out[b * TT + t] = p + outb[0];
}

// ---------------- host launcher ----------------
extern "C" void kernel_launch(void* const* d_in, const int* in_sizes, int n_in,
                              void* d_out, int out_size) {
    int off = (n_in >= 18 && in_sizes[1] == 1) ? 1 : 0;
    const float* enc_inputs = (const float*)d_in[0];
    const float* embed_W = (const float*)d_in[1 + off];
    const float* embed_b = (const float*)d_in[2 + off];
    const float* enc_Wih = (const float*)d_in[3 + off];
    const float* enc_Whh = (const float*)d_in[4 + off];
    const float* enc_bih = (const float*)d_in[5 + off];
    const float* enc_bhh = (const float*)d_in[6 + off];
    const float* dec_Wih = (const float*)d_in[7 + off];
    const float* dec_Whh = (const float*)d_in[8 + off];
    const float* dec_bih = (const float*)d_in[9 + off];
    const float* dec_bhh = (const float*)d_in[10 + off];
    const float* Wq = (const float*)d_in[11 + off];
    const float* bq = (const float*)d_in[12 + off];
    const float* Wk = (const float*)d_in[13 + off];
    // bk dropped: uniform over s -> softmax-invariant
    const float* out_W = (const float*)d_in[15 + off];
    const float* out_b = (const float*)d_in[16 + off];
    float* out = (float*)d_out;

    float* g_WkT_p; cudaGetSymbolAddress((void**)&g_WkT_p, g_WkT);
    float* g_WqT_p; cudaGetSymbolAddress((void**)&g_WqT_p, g_WqT);

    cudaFuncSetAttribute(lstm_mma<HH, 0>, cudaFuncAttributeMaxDynamicSharedMemorySize, SMEM_BYTES);
    cudaFuncSetAttribute(lstm_mma<K2, 1>, cudaFuncAttributeMaxDynamicSharedMemorySize, SMEM_BYTES);

    // ---- prep ----
    k_zero<<<(BB * HH + 255) / 256, 256>>>();
    k_vu<<<GG / 256, 256>>>(embed_W, embed_b, enc_Wih, enc_bih, enc_bhh);
    k_wenc_split<<<(GG * HH) / 256, 256>>>(enc_Whh);
    k_wdec_split<<<(GG * K2) / 256, 256>>>(dec_Wih, dec_Whh, dec_bih, dec_bhh);
    k_bqk<<<2, 256>>>(bq, Wk);
    dim3 tb(32, 8);
    k_transpose512<<<dim3(16, 16), tb>>>(Wk, g_WkT_p);
    k_transpose512<<<dim3(16, 16), tb>>>(Wq, g_WqT_p);
    k_gemm_At<<<dim3(16, 16), 256>>>();

    dim3 lgrid(GG / 64, BB / 64);   // 32 x 4

    // ---- encoder: 512 recurrent steps on HMMA tensor path ----
    for (int s = 0; s < SS; ++s)
        lstm_mma<HH, 0><<<lgrid, 256, SMEM_BYTES>>>(enc_inputs, s & 1, s);

    // ---- decoder: 96 steps ----
    for (int t = 0; t < TT; ++t) {
        int par = t & 1;
        k_gemm_q2<<<dim3(HH / 32, BB / 32), 256>>>(par);
        k_attn<<<BB, 256>>>();
        lstm_mma<K2, 1><<<lgrid, 256, SMEM_BYTES>>>(nullptr, par, 0);
        k_out<<<BB / 8, 256>>>(par ^ 1, out_W, out_b, out, t);
    }
    (void)in_sizes; (void)n_in; (void)out_size;
}

// round 5
// speedup vs baseline: 1.8065x; 1.2566x over previous
#include <cuda_runtime.h>
#include <cuda_bf16.h>
#include <math.h>
#include <stdint.h>

#define BB 256
#define SS 512
#define RR 128
#define HH 512
#define TT 96
#define GG 2048   // 4*H
#define K2 1024   // 2*H

// ---------------- device scratch ----------------
__device__ float g_hs[(size_t)SS * BB * HH];        // encoder hidden states [s][b][h] fp32
__device__ float g_hbuf[2][BB * HH];                // ping-pong hidden (fp32, for q2/out)
__device__ float g_c[BB * HH];                      // cell state fp32 (decoder)
__device__ __nv_bfloat16 g_hhi[2][BB * HH], g_hlo[2][BB * HH];   // split-bf16 h ping-pong
__device__ __nv_bfloat16 g_ctxhi[BB * HH], g_ctxlo[BB * HH];     // split-bf16 context
__device__ __nv_bfloat16 g_Wenc_hi[GG * HH],  g_Wenc_lo[GG * HH];   // gate-interleaved enc Whh
__device__ __nv_bfloat16 g_Wdec_hi[GG * K2],  g_Wdec_lo[GG * K2];   // gate-interleaved dec (Wih+Whh)
__device__ float g_v2[GG], g_u2[GG], g_bd2[GG];     // gate-interleaved rank-1 input / biases
__device__ float g_WkT[HH * HH], g_WqT[HH * HH], g_At[HH * HH];
__device__ float g_bqk[HH];
__device__ float g_q2[BB * HH];

// grid-wide barrier state (persists across graph replays; gen compared by equality)
__device__ unsigned g_bar_count = 0;
__device__ volatile unsigned g_bar_gen = 0;

// ---------------- helpers ----------------
__device__ __forceinline__ uint32_t smem_u32(const void* p) {
    uint32_t a;
    asm("{ .reg .u64 t; cvta.to.shared.u64 t, %1; cvt.u32.u64 %0, t; }" : "=r"(a) : "l"(p));
    return a;
}
__device__ __forceinline__ void cp16(uint32_t dst, const void* src) {
    asm volatile("cp.async.cg.shared.global [%0], [%1], 16;" :: "r"(dst), "l"(src) : "memory");
}
#define CP_COMMIT() asm volatile("cp.async.commit_group;" ::: "memory")
#define CP_WAIT1()  asm volatile("cp.async.wait_group 1;" ::: "memory")
#define CP_WAIT0()  asm volatile("cp.async.wait_group 0;" ::: "memory")

__device__ __forceinline__ void ldm4(uint32_t* r, uint32_t addr) {
    asm volatile("ldmatrix.sync.aligned.m8n8.x4.shared.b16 {%0,%1,%2,%3}, [%4];"
                 : "=r"(r[0]), "=r"(r[1]), "=r"(r[2]), "=r"(r[3]) : "r"(addr));
}
__device__ __forceinline__ void mma16816(float* c, const uint32_t* a, uint32_t b0, uint32_t b1) {
    asm volatile(
        "mma.sync.aligned.m16n8k16.row.col.f32.bf16.bf16.f32 "
        "{%0,%1,%2,%3}, {%4,%5,%6,%7}, {%8,%9}, {%0,%1,%2,%3};"
        : "+f"(c[0]), "+f"(c[1]), "+f"(c[2]), "+f"(c[3])
        : "r"(a[0]), "r"(a[1]), "r"(a[2]), "r"(a[3]), "r"(b0), "r"(b1));
}

__device__ __forceinline__ void grid_sync(unsigned nct) {
    __syncthreads();
    if (threadIdx.x == 0) {
        __threadfence();                               // release: h stores visible
        unsigned gen = g_bar_gen;
        unsigned t = atomicInc(&g_bar_count, nct - 1); // wraps to 0 at nct-1
        if (t == nct - 1) {
            g_bar_gen = gen + 1;
        } else {
            while (g_bar_gen == gen) __nanosleep(64);
        }
        __threadfence();                               // acquire
    }
    __syncthreads();
}

// tile geometry (shared by persistent encoder and decoder GEMM)
#define T_ROW   144
#define T_SZ    (64 * T_ROW)          // 9216

// ---- decoder lstm kernel smem (double-buffered 4 tiles) ----
#define TA_HI   0
#define TA_LO   (1 * T_SZ)
#define TB_HI   (2 * T_SZ)
#define TB_LO   (3 * T_SZ)
#define BUFS    (4 * T_SZ)            // 36864
#define SMEM_BYTES (2 * BUFS)         // 73728

// ---- persistent encoder smem ----
#define W_TILE  (8 * T_SZ)            // 73728 (64 rows x 512 k, chunked)
#define A_OFF   (2 * W_TILE)          // 147456
#define PSMEM   (A_OFF + 4 * T_SZ)    // 184320

// ================= persistent encoder: weights in SMEM, c in registers =================
// 512 recurrent steps in ONE kernel. Grid MUST be (32, 4) = 128 CTAs (all co-resident).
__global__ __launch_bounds__(256) void lstm_enc_persist(const float* __restrict__ enc_inputs) {
    extern __shared__ char smem[];
    uint32_t sb = smem_u32(smem);
    int tid = threadIdx.x;
    int w = tid >> 5, l = tid & 31;
    int n0 = blockIdx.x * 64;
    int m0 = blockIdx.y * 64;
    int mrow = (w & 3) * 16;
    int ncol = (w >> 2) * 32;

    // ---- load weight slice (64 n-rows x 512 k, hi+lo) into SMEM once ----
    for (int i = tid; i < 4096; i += 256) {       // 16B units: 8 chunks x 64 rows x 8 units
        int c = i >> 9, r = (i >> 3) & 63, cu = i & 7;
        uint32_t d = sb + c * T_SZ + r * T_ROW + cu * 16;
        size_t src = (size_t)(n0 + r) * HH + c * 64 + cu * 8;
        cp16(d, g_Wenc_hi + src);
        cp16(d + W_TILE, g_Wenc_lo + src);
    }
    CP_COMMIT();
    CP_WAIT0();
    __syncthreads();

    // epilogue ownership: thread -> (b, 4 h's); cell state lives in registers
    int bl_ = tid & 63;
    int q0 = (tid >> 6) * 4;
    int b = m0 + bl_;
    int hbase = n0 >> 2;
    float creg[4] = {0.f, 0.f, 0.f, 0.f};
    uint32_t rowsel = (l & 15) * T_ROW + (l >> 4) * 16;

    for (int s = 0; s < SS; ++s) {
        int par = s & 1, op = par ^ 1;
        const __nv_bfloat16* __restrict__ ah = g_hhi[par];
        const __nv_bfloat16* __restrict__ al = g_hlo[par];

        float acc[4][4];
#pragma unroll
        for (int nt = 0; nt < 4; ++nt)
#pragma unroll
            for (int r = 0; r < 4; ++r) acc[nt][r] = 0.f;

        auto issueA = [&](int c) {
            if (c < 8) {
                int c0 = c * 64;
                uint32_t buf = sb + A_OFF + (c & 1) * 2 * T_SZ;
#pragma unroll
                for (int i = 0; i < 2; ++i) {
                    int e = tid + i * 256;        // 0..511
                    int r = e >> 3, cu = e & 7;
                    uint32_t d = buf + r * T_ROW + cu * 16;
                    const __nv_bfloat16* srow = ah + (m0 + r) * HH + c0 + cu * 8;
                    cp16(d, srow);
                    cp16(d + T_SZ, al + (m0 + r) * HH + c0 + cu * 8);
                }
            }
            CP_COMMIT();
        };

        issueA(0);
        for (int c = 0; c < 8; ++c) {
            issueA(c + 1);
            CP_WAIT1();
            __syncthreads();
            uint32_t abase = sb + A_OFF + (c & 1) * 2 * T_SZ;
            uint32_t wbase = sb + c * T_SZ;
#pragma unroll
            for (int kk = 0; kk < 4; ++kk) {
                uint32_t kof = kk * 32;
                uint32_t aaddr = abase + mrow * T_ROW + rowsel + kof;
                uint32_t baddr = wbase + ncol * T_ROW + rowsel + kof;
                uint32_t ahr[4], alr[4], bh[8], bl2[8];
                ldm4(ahr, aaddr);
                ldm4(alr, aaddr + T_SZ);
                ldm4(bh, baddr);
                ldm4(bh + 4, baddr + 16 * T_ROW);
                ldm4(bl2, baddr + W_TILE);
                ldm4(bl2 + 4, baddr + W_TILE + 16 * T_ROW);
#pragma unroll
                for (int nt = 0; nt < 4; ++nt) {
                    uint32_t b0h = bh[(nt & 1) + (nt >> 1) * 4];
                    uint32_t b1h = bh[(nt & 1) + (nt >> 1) * 4 + 2];
                    uint32_t b0l = bl2[(nt & 1) + (nt >> 1) * 4];
                    uint32_t b1l = bl2[(nt & 1) + (nt >> 1) * 4 + 2];
                    mma16816(acc[nt], ahr, b0h, b1h);
                    mma16816(acc[nt], alr, b0h, b1h);
                    mma16816(acc[nt], ahr, b0l, b1l);
                }
            }
            __syncthreads();
        }

        // ---- epilogue: stage accums in (reused) A-buffer smem, LSTM cell, write h ----
        float* Cs = (float*)(smem + A_OFF);   // 64 x 68 fp32 = 17.4KB <= 36.8KB
        {
            int g = l >> 2, cc = l & 3;
#pragma unroll
            for (int nt = 0; nt < 4; ++nt) {
                int col = ncol + nt * 8 + cc * 2;
                int r0 = mrow + g, r1 = mrow + g + 8;
                Cs[r0 * 68 + col]     = acc[nt][0];
                Cs[r0 * 68 + col + 1] = acc[nt][1];
                Cs[r1 * 68 + col]     = acc[nt][2];
                Cs[r1 * 68 + col + 1] = acc[nt][3];
            }
        }
        __syncthreads();

        float e = enc_inputs[b * SS + s];
#pragma unroll
        for (int q = 0; q < 4; ++q) {
            int hl = q0 + q;
            int jl = hl * 4;
            int jp = n0 + jl;
            float ri = Cs[bl_ * 68 + jl + 0] + e * g_v2[jp + 0] + g_u2[jp + 0];
            float rf = Cs[bl_ * 68 + jl + 1] + e * g_v2[jp + 1] + g_u2[jp + 1];
            float rg = Cs[bl_ * 68 + jl + 2] + e * g_v2[jp + 2] + g_u2[jp + 2];
            float ro = Cs[bl_ * 68 + jl + 3] + e * g_v2[jp + 3] + g_u2[jp + 3];
            float ig = 1.f / (1.f + expf(-ri));
            float fg = 1.f / (1.f + expf(-rf));
            float gg = tanhf(rg);
            float og = 1.f / (1.f + expf(-ro));
            float cn = fg * creg[q] + ig * gg;
            float hn = og * tanhf(cn);
            creg[q] = cn;
            int idx = b * HH + hbase + hl;
            __nv_bfloat16 hi = __float2bfloat16(hn);
            g_hhi[op][idx] = hi;
            g_hlo[op][idx] = __float2bfloat16(hn - __bfloat162float(hi));
            g_hs[((size_t)s * BB + b) * HH + hbase + hl] = hn;
            if (s == SS - 1) { g_c[idx] = cn; g_hbuf[op][idx] = hn; }
        }
        grid_sync(128);
    }
}

// ================= decoder fused HMMA split-bf16 GEMM + LSTM cell (per step) =================
template <int KDIM>
__global__ __launch_bounds__(256) void lstm_mma_dec(int par) {
    constexpr int NCH = KDIM / 64;
    extern __shared__ char smem[];
    uint32_t sb = smem_u32(smem);

    int tid = threadIdx.x;
    int w = tid >> 5, l = tid & 31;
    int n0 = blockIdx.x * 64;
    int m0 = blockIdx.y * 64;
    int mrow = (w & 3) * 16;
    int ncol = (w >> 2) * 32;

    float acc[4][4];
#pragma unroll
    for (int nt = 0; nt < 4; ++nt)
#pragma unroll
        for (int r = 0; r < 4; ++r) acc[nt][r] = 0.f;

    auto issue = [&](int c) {
        if (c < NCH) {
            int c0 = c * 64;
            const __nv_bfloat16 *ah, *al;
            int ac0;
            if (c0 >= HH) { ah = g_ctxhi; al = g_ctxlo; ac0 = c0 - HH; }
            else          { ah = g_hhi[par]; al = g_hlo[par]; ac0 = c0; }
            uint32_t buf = sb + (c & 1) * BUFS;
#pragma unroll
            for (int i = 0; i < 2; ++i) {
                int e = tid + i * 256;
                int r = e >> 3, cu = e & 7;
                uint32_t d = buf + r * T_ROW + cu * 16;
                cp16(d + TA_HI, ah + (m0 + r) * HH + ac0 + cu * 8);
                cp16(d + TA_LO, al + (m0 + r) * HH + ac0 + cu * 8);
                cp16(d + TB_HI, g_Wdec_hi + (size_t)(n0 + r) * KDIM + c0 + cu * 8);
                cp16(d + TB_LO, g_Wdec_lo + (size_t)(n0 + r) * KDIM + c0 + cu * 8);
            }
        }
        CP_COMMIT();
    };

    issue(0);
    for (int c = 0; c < NCH; ++c) {
        issue(c + 1);
        CP_WAIT1();
        __syncthreads();
        uint32_t base = sb + (c & 1) * BUFS;
        uint32_t rowsel = (l & 15) * T_ROW + (l >> 4) * 16;
#pragma unroll
        for (int kk = 0; kk < 4; ++kk) {
            uint32_t kof = kk * 32;
            uint32_t aaddr = base + TA_HI + mrow * T_ROW + rowsel + kof;
            uint32_t baddr = base + TB_HI + ncol * T_ROW + rowsel + kof;
            uint32_t ah[4], al[4], bh[8], bl[8];
            ldm4(ah, aaddr);
            ldm4(al, aaddr + (TA_LO - TA_HI));
            ldm4(bh, baddr);
            ldm4(bh + 4, baddr + 16 * T_ROW);
            ldm4(bl, baddr + (TB_LO - TB_HI));
            ldm4(bl + 4, baddr + (TB_LO - TB_HI) + 16 * T_ROW);
#pragma unroll
            for (int nt = 0; nt < 4; ++nt) {
                uint32_t b0h = bh[(nt & 1) + (nt >> 1) * 4];
                uint32_t b1h = bh[(nt & 1) + (nt >> 1) * 4 + 2];
                uint32_t b0l = bl[(nt & 1) + (nt >> 1) * 4];
                uint32_t b1l = bl[(nt & 1) + (nt >> 1) * 4 + 2];
                mma16816(acc[nt], ah, b0h, b1h);
                mma16816(acc[nt], al, b0h, b1h);
                mma16816(acc[nt], ah, b0l, b1l);
            }
        }
        __syncthreads();
    }

    float* Cs = (float*)smem;
    {
        int g = l >> 2, cc = l & 3;
#pragma unroll
        for (int nt = 0; nt < 4; ++nt) {
            int col = ncol + nt * 8 + cc * 2;
            int r0 = mrow + g, r1 = mrow + g + 8;
            Cs[r0 * 68 + col]     = acc[nt][0];
            Cs[r0 * 68 + col + 1] = acc[nt][1];
            Cs[r1 * 68 + col]     = acc[nt][2];
            Cs[r1 * 68 + col + 1] = acc[nt][3];
        }
    }
    __syncthreads();

    int bl_ = tid & 63;
    int q0 = (tid >> 6) * 4;
    int b = m0 + bl_;
    int hbase = n0 >> 2;
    int op = par ^ 1;
#pragma unroll
    for (int q = 0; q < 4; ++q) {
        int hl = q0 + q;
        int jl = hl * 4;
        int jp = n0 + jl;
        float ri = Cs[bl_ * 68 + jl + 0] + g_bd2[jp + 0];
        float rf = Cs[bl_ * 68 + jl + 1] + g_bd2[jp + 1];
        float rg = Cs[bl_ * 68 + jl + 2] + g_bd2[jp + 2];
        float ro = Cs[bl_ * 68 + jl + 3] + g_bd2[jp + 3];
        float ig = 1.f / (1.f + expf(-ri));
        float fg = 1.f / (1.f + expf(-rf));
        float gg = tanhf(rg);
        float og = 1.f / (1.f + expf(-ro));
        int idx = b * HH + hbase + hl;
        float cn = fg * g_c[idx] + ig * gg;
        float hn = og * tanhf(cn);
        g_c[idx] = cn;
        g_hbuf[op][idx] = hn;
        __nv_bfloat16 hi = __float2bfloat16(hn);
        g_hhi[op][idx] = hi;
        g_hlo[op][idx] = __float2bfloat16(hn - __bfloat162float(hi));
    }
}

// ---------------- prep kernels ----------------
__global__ void k_zero() {
    int idx = blockIdx.x * 256 + threadIdx.x;
    if (idx < BB * HH) {
        g_c[idx] = 0.f;
        g_hhi[0][idx] = __float2bfloat16(0.f);
        g_hlo[0][idx] = __float2bfloat16(0.f);
    }
}

__global__ void k_vu(const float* __restrict__ embW, const float* __restrict__ embb,
                     const float* __restrict__ Wih, const float* __restrict__ bih,
                     const float* __restrict__ bhh) {
    int j = blockIdx.x * 256 + threadIdx.x;
    if (j >= GG) return;
    float v = 0.f, u = 0.f;
    const float* wr = Wih + j * RR;
#pragma unroll 8
    for (int r = 0; r < RR; ++r) { v += embW[r] * wr[r]; u += embb[r] * wr[r]; }
    int jp = ((j & (HH - 1)) << 2) | (j >> 9);   // j = g*H+h -> j' = h*4+g
    g_v2[jp] = v;
    g_u2[jp] = u + bih[j] + bhh[j];
}

__global__ void k_wenc_split(const float* __restrict__ Whh) {
    int idx = blockIdx.x * 256 + threadIdx.x;
    if (idx >= GG * HH) return;
    int jp = idx >> 9, k = idx & (HH - 1);
    int h = jp >> 2, g = jp & 3;
    float w = Whh[(g * HH + h) * HH + k];
    __nv_bfloat16 hi = __float2bfloat16(w);
    g_Wenc_hi[idx] = hi;
    g_Wenc_lo[idx] = __float2bfloat16(w - __bfloat162float(hi));
}

__global__ void k_wdec_split(const float* __restrict__ dWih, const float* __restrict__ dWhh,
                             const float* __restrict__ dbih, const float* __restrict__ dbhh) {
    int idx = blockIdx.x * 256 + threadIdx.x;
    if (idx < GG * K2) {
        int jp = idx >> 10, k = idx & (K2 - 1);
        int h = jp >> 2, g = jp & 3;
        float w = dWih[(g * HH + h) * K2 + k];
        if (k < HH) w += dWhh[(g * HH + h) * HH + k];
        __nv_bfloat16 hi = __float2bfloat16(w);
        g_Wdec_hi[idx] = hi;
        g_Wdec_lo[idx] = __float2bfloat16(w - __bfloat162float(hi));
    }
    if (idx < GG) {
        int h = idx >> 2, g = idx & 3;
        g_bd2[idx] = dbih[g * HH + h] + dbhh[g * HH + h];
    }
}

__global__ void k_bqk(const float* __restrict__ bq, const float* __restrict__ Wk) {
    int m = blockIdx.x * 256 + threadIdx.x;
    if (m >= HH) return;
    float a = 0.f;
    for (int n = 0; n < HH; ++n) a += bq[n] * Wk[n * HH + m];
    g_bqk[m] = a;
}

__global__ void k_transpose512(const float* __restrict__ in, float* __restrict__ out) {
    __shared__ float t[32][33];
    int x = blockIdx.x * 32 + threadIdx.x;
    int y0 = blockIdx.y * 32;
    for (int j = threadIdx.y; j < 32; j += 8) t[j][threadIdx.x] = in[(y0 + j) * HH + x];
    __syncthreads();
    int x2 = y0 + threadIdx.x;
    int y20 = blockIdx.x * 32;
    for (int j = threadIdx.y; j < 32; j += 8) out[(y20 + j) * HH + x2] = t[threadIdx.x][j];
}

// ---------------- 32x32-tile fp32 GEMM: C[m][n] = sum_k A[m][k]*Bw[n][k] (+bias[n]) ----------------
__device__ __forceinline__ void gemm32_core(const float* __restrict__ A,
                                            const float* __restrict__ Bw,
                                            const float* __restrict__ bias,
                                            float* __restrict__ C, int N, int K) {
    __shared__ float As[32][33];
    __shared__ float Bs[32][33];
    int tid = threadIdx.x;
    int m0 = blockIdx.y * 32, n0 = blockIdx.x * 32;
    int lr = tid >> 3, lk = (tid & 7) << 2;
    int ty = tid >> 4, tx = tid & 15;
    float acc00 = 0.f, acc01 = 0.f, acc10 = 0.f, acc11 = 0.f;
    for (int kk = 0; kk < K; kk += 32) {
        float4 a = *(const float4*)(A + (m0 + lr) * K + kk + lk);
        float4 b = *(const float4*)(Bw + (n0 + lr) * K + kk + lk);
        __syncthreads();
        As[lk + 0][lr] = a.x; As[lk + 1][lr] = a.y; As[lk + 2][lr] = a.z; As[lk + 3][lr] = a.w;
        Bs[lk + 0][lr] = b.x; Bs[lk + 1][lr] = b.y; Bs[lk + 2][lr] = b.z; Bs[lk + 3][lr] = b.w;
        __syncthreads();
#pragma unroll
        for (int k = 0; k < 32; ++k) {
            float a0 = As[k][ty * 2], a1 = As[k][ty * 2 + 1];
            float b0 = Bs[k][tx * 2], b1 = Bs[k][tx * 2 + 1];
            acc00 += a0 * b0; acc01 += a0 * b1;
            acc10 += a1 * b0; acc11 += a1 * b1;
        }
    }
    float bb0 = bias ? bias[n0 + tx * 2] : 0.f;
    float bb1 = bias ? bias[n0 + tx * 2 + 1] : 0.f;
    C[(m0 + ty * 2 + 0) * N + n0 + tx * 2 + 0] = acc00 + bb0;
    C[(m0 + ty * 2 + 0) * N + n0 + tx * 2 + 1] = acc01 + bb1;
    C[(m0 + ty * 2 + 1) * N + n0 + tx * 2 + 0] = acc10 + bb0;
    C[(m0 + ty * 2 + 1) * N + n0 + tx * 2 + 1] = acc11 + bb1;
}

__global__ __launch_bounds__(256) void k_gemm_At() {
    gemm32_core(g_WkT, g_WqT, nullptr, g_At, HH, HH);
}
__global__ __launch_bounds__(256) void k_gemm_q2(int par) {
    gemm32_core(g_hbuf[par], g_At, g_bqk, g_q2, HH, HH);
}

// ---------------- one-pass online-softmax attention ----------------
__global__ __launch_bounds__(256) void k_attn() {
    int b = blockIdx.x;
    int tid = threadIdx.x;
    int w = tid >> 5, ln = tid & 31;

    const float4* q4 = (const float4*)(g_q2 + b * HH + ln * 16);
    float4 q0 = q4[0], q1 = q4[1], q2v = q4[2], q3 = q4[3];

    float m = -INFINITY, l = 0.f;
    float ca[16];
#pragma unroll
    for (int q = 0; q < 16; ++q) ca[q] = 0.f;

    for (int it = 0; it < SS / 8; ++it) {
        int s = w + (it << 3);
        const float4* r4 = (const float4*)(g_hs + ((size_t)s * BB + b) * HH + ln * 16);
        float4 r0 = r4[0], r1 = r4[1], r2 = r4[2], r3 = r4[3];
        float dot = r0.x * q0.x + r0.y * q0.y + r0.z * q0.z + r0.w * q0.w
                  + r1.x * q1.x + r1.y * q1.y + r1.z * q1.z + r1.w * q1.w
                  + r2.x * q2v.x + r2.y * q2v.y + r2.z * q2v.z + r2.w * q2v.w
                  + r3.x * q3.x + r3.y * q3.y + r3.z * q3.z + r3.w * q3.w;
#pragma unroll
        for (int off = 16; off; off >>= 1) dot += __shfl_xor_sync(0xffffffffu, dot, off);
        float mn = fmaxf(m, dot);
        float scl = __expf(m - mn);
        float p = __expf(dot - mn);
        m = mn;
        l = l * scl + p;
        float rr[16] = {r0.x, r0.y, r0.z, r0.w, r1.x, r1.y, r1.z, r1.w,
                        r2.x, r2.y, r2.z, r2.w, r3.x, r3.y, r3.z, r3.w};
#pragma unroll
        for (int q = 0; q < 16; ++q) ca[q] = ca[q] * scl + p * rr[q];
    }

    __shared__ float sm[8], sl[8];
    __shared__ float sc[8][HH];
#pragma unroll
    for (int q = 0; q < 16; ++q) sc[w][ln * 16 + q] = ca[q];
    if (ln == 0) { sm[w] = m; sl[w] = l; }
    __syncthreads();

    float M = sm[0];
#pragma unroll
    for (int w2 = 1; w2 < 8; ++w2) M = fmaxf(M, sm[w2]);
    float ew[8];
    float L = 0.f;
#pragma unroll
    for (int w2 = 0; w2 < 8; ++w2) { ew[w2] = __expf(sm[w2] - M); L += sl[w2] * ew[w2]; }
    float invL = 1.f / L;
    for (int h = tid; h < HH; h += 256) {
        float v = 0.f;
#pragma unroll
        for (int w2 = 0; w2 < 8; ++w2) v += ew[w2] * sc[w2][h];
        v *= invL;
        __nv_bfloat16 hi = __float2bfloat16(v);
        g_ctxhi[b * HH + h] = hi;
        g_ctxlo[b * HH + h] = __float2bfloat16(v - __bfloat162float(hi));
    }
}

// ---------------- output projection ----------------
__global__ void k_out(int par, const float* __restrict__ outW, const float* __restrict__ outb,
                      float* __restrict__ out, int t) {
    int tid = threadIdx.x;
    int b = blockIdx.x * 8 + (tid >> 5);
    int ln = tid & 31;
    const float* hp = g_hbuf[par] + b * HH;
    float p = 0.f;
#pragma unroll
    for (int q = 0; q < 16; ++q) p += hp[ln + (q << 5)] * outW[ln + (q << 5)];
#pragma unroll
    for (int off = 16; off; off >>= 1) p += __shfl_xor_sync(0xffffffffu, p, off);
    if (ln == 0) out[b * TT + t] = p + outb[0];
}

// ---------------- host launcher ----------------
extern "C" void kernel_launch(void* const* d_in, const int* in_sizes, int n_in,
                              void* d_out, int out_size) {
    int off = (n_in >= 18 && in_sizes[1] == 1) ? 1 : 0;
    const float* enc_inputs = (const float*)d_in[0];
    const float* embed_W = (const float*)d_in[1 + off];
    const float* embed_b = (const float*)d_in[2 + off];
    const float* enc_Wih = (const float*)d_in[3 + off];
    const float* enc_Whh = (const float*)d_in[4 + off];
    const float* enc_bih = (const float*)d_in[5 + off];
    const float* enc_bhh = (const float*)d_in[6 + off];
    const float* dec_Wih = (const float*)d_in[7 + off];
    const float* dec_Whh = (const float*)d_in[8 + off];
    const float* dec_bih = (const float*)d_in[9 + off];
    const float* dec_bhh = (const float*)d_in[10 + off];
    const float* Wq = (const float*)d_in[11 + off];
    const float* bq = (const float*)d_in[12 + off];
    const float* Wk = (const float*)d_in[13 + off];
    // bk dropped: uniform over s -> softmax-invariant
    const float* out_W = (const float*)d_in[15 + off];
    const float* out_b = (const float*)d_in[16 + off];
    float* out = (float*)d_out;

    float* g_WkT_p; cudaGetSymbolAddress((void**)&g_WkT_p, g_WkT);
    float* g_WqT_p; cudaGetSymbolAddress((void**)&g_WqT_p, g_WqT);

    cudaFuncSetAttribute(lstm_enc_persist, cudaFuncAttributeMaxDynamicSharedMemorySize, PSMEM);
    cudaFuncSetAttribute(lstm_mma_dec<K2>, cudaFuncAttributeMaxDynamicSharedMemorySize, SMEM_BYTES);

    // ---- prep ----
    k_zero<<<(BB * HH + 255) / 256, 256>>>();
    k_vu<<<GG / 256, 256>>>(embed_W, embed_b, enc_Wih, enc_bih, enc_bhh);
    k_wenc_split<<<(GG * HH) / 256, 256>>>(enc_Whh);
    k_wdec_split<<<(GG * K2) / 256, 256>>>(dec_Wih, dec_Whh, dec_bih, dec_bhh);
    k_bqk<<<2, 256>>>(bq, Wk);
    dim3 tb(32, 8);
    k_transpose512<<<dim3(16, 16), tb>>>(Wk, g_WkT_p);
    k_transpose512<<<dim3(16, 16), tb>>>(Wq, g_WqT_p);
    k_gemm_At<<<dim3(16, 16), 256>>>();

    // ---- encoder: ONE persistent kernel, 512 internal steps ----
    lstm_enc_persist<<<dim3(32, 4), 256, PSMEM>>>(enc_inputs);

    // ---- decoder: 96 steps ----
    dim3 lgrid(GG / 64, BB / 64);   // 32 x 4
    for (int t = 0; t < TT; ++t) {
        int par = t & 1;
        k_gemm_q2<<<dim3(HH / 32, BB / 32), 256>>>(par);
        k_attn<<<BB, 256>>>();
        lstm_mma_dec<K2><<<lgrid, 256, SMEM_BYTES>>>(par);
        k_out<<<BB / 8, 256>>>(par ^ 1, out_W, out_b, out, t);
    }
    (void)in_sizes; (void)n_in; (void)out_size;
}

// round 6
// speedup vs baseline: 2.2181x; 1.2278x over previous
#include <cuda_runtime.h>
#include <cuda_bf16.h>
#include <math.h>
#include <stdint.h>

#define BB 256
#define SS 512
#define RR 128
#define HH 512
#define TT 96
#define GG 2048   // 4*H
#define K2 1024   // 2*H

// ---------------- device scratch ----------------
__device__ __nv_bfloat16 g_hsb[(size_t)SS * BB * HH];   // encoder hidden states bf16 [s][b][h]
__device__ float g_hbuf[2][BB * HH];                    // ping-pong hidden fp32 (for k_out)
__device__ float g_c[BB * HH];                          // cell state fp32 (decoder)
__device__ __nv_bfloat16 g_hhi[2][BB * HH], g_hlo[2][BB * HH];   // split-bf16 h ping-pong
__device__ __nv_bfloat16 g_ctxhi[BB * HH], g_ctxlo[BB * HH];     // split-bf16 context
__device__ __nv_bfloat16 g_Wenc_hi[GG * HH],  g_Wenc_lo[GG * HH];
__device__ __nv_bfloat16 g_Wdec_hi[GG * K2],  g_Wdec_lo[GG * K2];
__device__ __nv_bfloat16 g_Athi[HH * HH], g_Atlo[HH * HH];       // split At for q2
__device__ float g_v2[GG], g_u2[GG], g_bd2[GG];
__device__ float g_WkT[HH * HH], g_WqT[HH * HH], g_At[HH * HH];
__device__ float g_bqk[HH];
__device__ float g_q2[BB * HH];

// grid-wide barrier state
__device__ unsigned g_bar_count = 0;
__device__ volatile unsigned g_bar_gen = 0;

// ---------------- helpers ----------------
__device__ __forceinline__ uint32_t smem_u32(const void* p) {
    uint32_t a;
    asm("{ .reg .u64 t; cvta.to.shared.u64 t, %1; cvt.u32.u64 %0, t; }" : "=r"(a) : "l"(p));
    return a;
}
__device__ __forceinline__ void cp16(uint32_t dst, const void* src) {
    asm volatile("cp.async.cg.shared.global [%0], [%1], 16;" :: "r"(dst), "l"(src) : "memory");
}
#define CP_COMMIT() asm volatile("cp.async.commit_group;" ::: "memory")
#define CP_WAIT1()  asm volatile("cp.async.wait_group 1;" ::: "memory")
#define CP_WAIT0()  asm volatile("cp.async.wait_group 0;" ::: "memory")

__device__ __forceinline__ void ldm4(uint32_t* r, uint32_t addr) {
    asm volatile("ldmatrix.sync.aligned.m8n8.x4.shared.b16 {%0,%1,%2,%3}, [%4];"
                 : "=r"(r[0]), "=r"(r[1]), "=r"(r[2]), "=r"(r[3]) : "r"(addr));
}
__device__ __forceinline__ void mma16816(float* c, const uint32_t* a, uint32_t b0, uint32_t b1) {
    asm volatile(
        "mma.sync.aligned.m16n8k16.row.col.f32.bf16.bf16.f32 "
        "{%0,%1,%2,%3}, {%4,%5,%6,%7}, {%8,%9}, {%0,%1,%2,%3};"
        : "+f"(c[0]), "+f"(c[1]), "+f"(c[2]), "+f"(c[3])
        : "r"(a[0]), "r"(a[1]), "r"(a[2]), "r"(a[3]), "r"(b0), "r"(b1));
}

__device__ __forceinline__ void grid_sync(unsigned nct) {
    __syncthreads();
    if (threadIdx.x == 0) {
        __threadfence();
        unsigned gen = g_bar_gen;
        unsigned t = atomicInc(&g_bar_count, nct - 1);
        if (t == nct - 1) {
            g_bar_gen = gen + 1;
        } else {
            while (g_bar_gen == gen) __nanosleep(64);
        }
        __threadfence();
    }
    __syncthreads();
}

// tile geometry
#define T_ROW   144
#define T_SZ    (64 * T_ROW)          // 9216

// decoder/q2 smem (double-buffered 4 tiles)
#define TA_HI   0
#define TA_LO   (1 * T_SZ)
#define TB_HI   (2 * T_SZ)
#define TB_LO   (3 * T_SZ)
#define BUFS    (4 * T_SZ)            // 36864
#define SMEM_BYTES (2 * BUFS)         // 73728

// persistent encoder smem
#define W_TILE  (8 * T_SZ)            // 73728
#define A_OFF   (2 * W_TILE)          // 147456
#define PSMEM   (A_OFF + 4 * T_SZ)    // 184320

// ================= shared mainloop piece: one chunk of 16-warp 64x64 MMA =================
// warp layout: w 0..15, mrow=(w&3)*16, ncol=(w>>2)*16; acc[2][4]
__device__ __forceinline__ void chunk_mma_16w(uint32_t abase, uint32_t alo_off,
                                              uint32_t bbase, uint32_t blo_off,
                                              int mrow, int ncol, uint32_t rowsel,
                                              float acc[2][4]) {
#pragma unroll
    for (int kk = 0; kk < 4; ++kk) {
        uint32_t kof = kk * 32;
        uint32_t aaddr = abase + mrow * T_ROW + rowsel + kof;
        uint32_t baddr = bbase + ncol * T_ROW + rowsel + kof;
        uint32_t ahr[4], alr[4], bh[4], bl2[4];
        ldm4(ahr, aaddr);
        ldm4(alr, aaddr + alo_off);
        ldm4(bh, baddr);
        ldm4(bl2, baddr + blo_off);
#pragma unroll
        for (int nt = 0; nt < 2; ++nt) {
            mma16816(acc[nt], ahr, bh[nt], bh[nt + 2]);
            mma16816(acc[nt], alr, bh[nt], bh[nt + 2]);
            mma16816(acc[nt], ahr, bl2[nt], bl2[nt + 2]);
        }
    }
}

// ================= persistent encoder: weights in SMEM, c in registers =================
// Grid MUST be (32, 4) = 128 CTAs co-resident, 512 threads.
__global__ __launch_bounds__(512) void lstm_enc_persist(const float* __restrict__ enc_inputs) {
    extern __shared__ char smem[];
    uint32_t sb = smem_u32(smem);
    int tid = threadIdx.x;
    int w = tid >> 5, l = tid & 31;
    int n0 = blockIdx.x * 64;
    int m0 = blockIdx.y * 64;
    int mrow = (w & 3) * 16;
    int ncol = (w >> 2) * 16;

    // weight slice (64 rows x 512 k, hi+lo) -> SMEM once
    for (int i = tid; i < 4096; i += 512) {
        int c = i >> 9, r = (i >> 3) & 63, cu = i & 7;
        uint32_t d = sb + c * T_SZ + r * T_ROW + cu * 16;
        size_t src = (size_t)(n0 + r) * HH + c * 64 + cu * 8;
        cp16(d, g_Wenc_hi + src);
        cp16(d + W_TILE, g_Wenc_lo + src);
    }
    CP_COMMIT();
    CP_WAIT0();
    __syncthreads();

    int bl_ = tid & 63;
    int q0 = (tid >> 6) * 2;      // 2 h's per thread
    int b = m0 + bl_;
    int hbase = n0 >> 2;
    float creg[2] = {0.f, 0.f};
    uint32_t rowsel = (l & 15) * T_ROW + (l >> 4) * 16;

    for (int s = 0; s < SS; ++s) {
        int par = s & 1, op = par ^ 1;
        const __nv_bfloat16* __restrict__ ah = g_hhi[par];
        const __nv_bfloat16* __restrict__ al = g_hlo[par];

        float acc[2][4];
#pragma unroll
        for (int nt = 0; nt < 2; ++nt)
#pragma unroll
            for (int r = 0; r < 4; ++r) acc[nt][r] = 0.f;

        auto issueA = [&](int c) {
            if (c < 8) {
                int c0 = c * 64;
                uint32_t buf = sb + A_OFF + (c & 1) * 2 * T_SZ;
                int r = tid >> 3, cu = tid & 7;   // 512 units, 1/thread
                uint32_t d = buf + r * T_ROW + cu * 16;
                cp16(d, ah + (m0 + r) * HH + c0 + cu * 8);
                cp16(d + T_SZ, al + (m0 + r) * HH + c0 + cu * 8);
            }
            CP_COMMIT();
        };

        issueA(0);
        for (int c = 0; c < 8; ++c) {
            issueA(c + 1);
            CP_WAIT1();
            __syncthreads();
            uint32_t abase = sb + A_OFF + (c & 1) * 2 * T_SZ;
            uint32_t wbase = sb + c * T_SZ;
            chunk_mma_16w(abase, T_SZ, wbase, W_TILE, mrow, ncol, rowsel, acc);
            __syncthreads();
        }

        float* Cs = (float*)(smem + A_OFF);   // 64 x 68 fp32
        {
            int g = l >> 2, cc = l & 3;
#pragma unroll
            for (int nt = 0; nt < 2; ++nt) {
                int col = ncol + nt * 8 + cc * 2;
                int r0 = mrow + g, r1 = mrow + g + 8;
                Cs[r0 * 68 + col]     = acc[nt][0];
                Cs[r0 * 68 + col + 1] = acc[nt][1];
                Cs[r1 * 68 + col]     = acc[nt][2];
                Cs[r1 * 68 + col + 1] = acc[nt][3];
            }
        }
        __syncthreads();

        float e = enc_inputs[b * SS + s];
#pragma unroll
        for (int q = 0; q < 2; ++q) {
            int hl = q0 + q;
            int jl = hl * 4;
            int jp = n0 + jl;
            float ri = Cs[bl_ * 68 + jl + 0] + e * g_v2[jp + 0] + g_u2[jp + 0];
            float rf = Cs[bl_ * 68 + jl + 1] + e * g_v2[jp + 1] + g_u2[jp + 1];
            float rg = Cs[bl_ * 68 + jl + 2] + e * g_v2[jp + 2] + g_u2[jp + 2];
            float ro = Cs[bl_ * 68 + jl + 3] + e * g_v2[jp + 3] + g_u2[jp + 3];
            float ig = 1.f / (1.f + expf(-ri));
            float fg = 1.f / (1.f + expf(-rf));
            float gg = tanhf(rg);
            float og = 1.f / (1.f + expf(-ro));
            float cn = fg * creg[q] + ig * gg;
            float hn = og * tanhf(cn);
            creg[q] = cn;
            int idx = b * HH + hbase + hl;
            __nv_bfloat16 hi = __float2bfloat16(hn);
            g_hhi[op][idx] = hi;
            g_hlo[op][idx] = __float2bfloat16(hn - __bfloat162float(hi));
            g_hsb[((size_t)s * BB + b) * HH + hbase + hl] = hi;
            if (s == SS - 1) { g_c[idx] = cn; g_hbuf[op][idx] = hn; }
        }
        grid_sync(128);
    }
}

// ================= decoder fused GEMM + LSTM cell (per step), 512 threads =================
__global__ __launch_bounds__(512) void lstm_mma_dec(int par) {
    constexpr int NCH = K2 / 64;
    extern __shared__ char smem[];
    uint32_t sb = smem_u32(smem);

    int tid = threadIdx.x;
    int w = tid >> 5, l = tid & 31;
    int n0 = blockIdx.x * 64;
    int m0 = blockIdx.y * 64;
    int mrow = (w & 3) * 16;
    int ncol = (w >> 2) * 16;

    float acc[2][4];
#pragma unroll
    for (int nt = 0; nt < 2; ++nt)
#pragma unroll
        for (int r = 0; r < 4; ++r) acc[nt][r] = 0.f;

    auto issue = [&](int c) {
        if (c < NCH) {
            int c0 = c * 64;
            const __nv_bfloat16 *ah, *al;
            int ac0;
            if (c0 >= HH) { ah = g_ctxhi; al = g_ctxlo; ac0 = c0 - HH; }
            else          { ah = g_hhi[par]; al = g_hlo[par]; ac0 = c0; }
            uint32_t buf = sb + (c & 1) * BUFS;
            int r = tid >> 3, cu = tid & 7;
            uint32_t d = buf + r * T_ROW + cu * 16;
            cp16(d + TA_HI, ah + (m0 + r) * HH + ac0 + cu * 8);
            cp16(d + TA_LO, al + (m0 + r) * HH + ac0 + cu * 8);
            cp16(d + TB_HI, g_Wdec_hi + (size_t)(n0 + r) * K2 + c0 + cu * 8);
            cp16(d + TB_LO, g_Wdec_lo + (size_t)(n0 + r) * K2 + c0 + cu * 8);
        }
        CP_COMMIT();
    };

    uint32_t rowsel = (l & 15) * T_ROW + (l >> 4) * 16;
    issue(0);
    for (int c = 0; c < NCH; ++c) {
        issue(c + 1);
        CP_WAIT1();
        __syncthreads();
        uint32_t base = sb + (c & 1) * BUFS;
        chunk_mma_16w(base + TA_HI, TA_LO - TA_HI, base + TB_HI, TB_LO - TB_HI,
                      mrow, ncol, rowsel, acc);
        __syncthreads();
    }

    float* Cs = (float*)smem;
    {
        int g = l >> 2, cc = l & 3;
#pragma unroll
        for (int nt = 0; nt < 2; ++nt) {
            int col = ncol + nt * 8 + cc * 2;
            int r0 = mrow + g, r1 = mrow + g + 8;
            Cs[r0 * 68 + col]     = acc[nt][0];
            Cs[r0 * 68 + col + 1] = acc[nt][1];
            Cs[r1 * 68 + col]     = acc[nt][2];
            Cs[r1 * 68 + col + 1] = acc[nt][3];
        }
    }
    __syncthreads();

    int bl_ = tid & 63;
    int q0 = (tid >> 6) * 2;
    int b = m0 + bl_;
    int hbase = n0 >> 2;
    int op = par ^ 1;
#pragma unroll
    for (int q = 0; q < 2; ++q) {
        int hl = q0 + q;
        int jl = hl * 4;
        int jp = n0 + jl;
        float ri = Cs[bl_ * 68 + jl + 0] + g_bd2[jp + 0];
        float rf = Cs[bl_ * 68 + jl + 1] + g_bd2[jp + 1];
        float rg = Cs[bl_ * 68 + jl + 2] + g_bd2[jp + 2];
        float ro = Cs[bl_ * 68 + jl + 3] + g_bd2[jp + 3];
        float ig = 1.f / (1.f + expf(-ri));
        float fg = 1.f / (1.f + expf(-rf));
        float gg = tanhf(rg);
        float og = 1.f / (1.f + expf(-ro));
        int idx = b * HH + hbase + hl;
        float cn = fg * g_c[idx] + ig * gg;
        float hn = og * tanhf(cn);
        g_c[idx] = cn;
        g_hbuf[op][idx] = hn;
        __nv_bfloat16 hi = __float2bfloat16(hn);
        g_hhi[op][idx] = hi;
        g_hlo[op][idx] = __float2bfloat16(hn - __bfloat162float(hi));
    }
}

// ================= q2 = h @ At^T + bqk on HMMA, 512 threads, grid (8,4) =================
__global__ __launch_bounds__(512) void q2_mma(int par) {
    constexpr int NCH = HH / 64;
    extern __shared__ char smem[];
    uint32_t sb = smem_u32(smem);

    int tid = threadIdx.x;
    int w = tid >> 5, l = tid & 31;
    int n0 = blockIdx.x * 64;   // At m-rows
    int m0 = blockIdx.y * 64;   // batch
    int mrow = (w & 3) * 16;
    int ncol = (w >> 2) * 16;

    float acc[2][4];
#pragma unroll
    for (int nt = 0; nt < 2; ++nt)
#pragma unroll
        for (int r = 0; r < 4; ++r) acc[nt][r] = 0.f;

    auto issue = [&](int c) {
        if (c < NCH) {
            int c0 = c * 64;
            uint32_t buf = sb + (c & 1) * BUFS;
            int r = tid >> 3, cu = tid & 7;
            uint32_t d = buf + r * T_ROW + cu * 16;
            cp16(d + TA_HI, g_hhi[par] + (m0 + r) * HH + c0 + cu * 8);
            cp16(d + TA_LO, g_hlo[par] + (m0 + r) * HH + c0 + cu * 8);
            cp16(d + TB_HI, g_Athi + (size_t)(n0 + r) * HH + c0 + cu * 8);
            cp16(d + TB_LO, g_Atlo + (size_t)(n0 + r) * HH + c0 + cu * 8);
        }
        CP_COMMIT();
    };

    uint32_t rowsel = (l & 15) * T_ROW + (l >> 4) * 16;
    issue(0);
    for (int c = 0; c < NCH; ++c) {
        issue(c + 1);
        CP_WAIT1();
        __syncthreads();
        uint32_t base = sb + (c & 1) * BUFS;
        chunk_mma_16w(base + TA_HI, TA_LO - TA_HI, base + TB_HI, TB_LO - TB_HI,
                      mrow, ncol, rowsel, acc);
        __syncthreads();
    }

    int g = l >> 2, cc = l & 3;
#pragma unroll
    for (int nt = 0; nt < 2; ++nt) {
        int col = n0 + ncol + nt * 8 + cc * 2;
        int r0 = m0 + mrow + g, r1 = r0 + 8;
        float2 v0 = {acc[nt][0] + g_bqk[col], acc[nt][1] + g_bqk[col + 1]};
        float2 v1 = {acc[nt][2] + g_bqk[col], acc[nt][3] + g_bqk[col + 1]};
        *(float2*)(g_q2 + r0 * HH + col) = v0;
        *(float2*)(g_q2 + r1 * HH + col) = v1;
    }
}

// ---------------- prep kernels ----------------
__global__ void k_zero() {
    int idx = blockIdx.x * 256 + threadIdx.x;
    if (idx < BB * HH) {
        g_c[idx] = 0.f;
        g_hhi[0][idx] = __float2bfloat16(0.f);
        g_hlo[0][idx] = __float2bfloat16(0.f);
    }
}

__global__ void k_vu(const float* __restrict__ embW, const float* __restrict__ embb,
                     const float* __restrict__ Wih, const float* __restrict__ bih,
                     const float* __restrict__ bhh) {
    int j = blockIdx.x * 256 + threadIdx.x;
    if (j >= GG) return;
    float v = 0.f, u = 0.f;
    const float* wr = Wih + j * RR;
#pragma unroll 8
    for (int r = 0; r < RR; ++r) { v += embW[r] * wr[r]; u += embb[r] * wr[r]; }
    int jp = ((j & (HH - 1)) << 2) | (j >> 9);
    g_v2[jp] = v;
    g_u2[jp] = u + bih[j] + bhh[j];
}

__global__ void k_wenc_split(const float* __restrict__ Whh) {
    int idx = blockIdx.x * 256 + threadIdx.x;
    if (idx >= GG * HH) return;
    int jp = idx >> 9, k = idx & (HH - 1);
    int h = jp >> 2, g = jp & 3;
    float w = Whh[(g * HH + h) * HH + k];
    __nv_bfloat16 hi = __float2bfloat16(w);
    g_Wenc_hi[idx] = hi;
    g_Wenc_lo[idx] = __float2bfloat16(w - __bfloat162float(hi));
}

__global__ void k_wdec_split(const float* __restrict__ dWih, const float* __restrict__ dWhh,
                             const float* __restrict__ dbih, const float* __restrict__ dbhh) {
    int idx = blockIdx.x * 256 + threadIdx.x;
    if (idx < GG * K2) {
        int jp = idx >> 10, k = idx & (K2 - 1);
        int h = jp >> 2, g = jp & 3;
        float w = dWih[(g * HH + h) * K2 + k];
        if (k < HH) w += dWhh[(g * HH + h) * HH + k];
        __nv_bfloat16 hi = __float2bfloat16(w);
        g_Wdec_hi[idx] = hi;
        g_Wdec_lo[idx] = __float2bfloat16(w - __bfloat162float(hi));
    }
    if (idx < GG) {
        int h = idx >> 2, g = idx & 3;
        g_bd2[idx] = dbih[g * HH + h] + dbhh[g * HH + h];
    }
}

__global__ void k_bqk(const float* __restrict__ bq, const float* __restrict__ Wk) {
    int m = blockIdx.x * 256 + threadIdx.x;
    if (m >= HH) return;
    float a = 0.f;
    for (int n = 0; n < HH; ++n) a += bq[n] * Wk[n * HH + m];
    g_bqk[m] = a;
}

__global__ void k_transpose512(const float* __restrict__ in, float* __restrict__ out) {
    __shared__ float t[32][33];
    int x = blockIdx.x * 32 + threadIdx.x;
    int y0 = blockIdx.y * 32;
    for (int j = threadIdx.y; j < 32; j += 8) t[j][threadIdx.x] = in[(y0 + j) * HH + x];
    __syncthreads();
    int x2 = y0 + threadIdx.x;
    int y20 = blockIdx.x * 32;
    for (int j = threadIdx.y; j < 32; j += 8) out[(y20 + j) * HH + x2] = t[threadIdx.x][j];
}

__global__ void k_at_split() {
    int idx = blockIdx.x * 256 + threadIdx.x;
    if (idx >= HH * HH) return;
    float w = g_At[idx];
    __nv_bfloat16 hi = __float2bfloat16(w);
    g_Athi[idx] = hi;
    g_Atlo[idx] = __float2bfloat16(w - __bfloat162float(hi));
}

// ---------------- 32x32-tile fp32 GEMM (prep only) ----------------
__global__ __launch_bounds__(256) void k_gemm_At() {
    __shared__ float As[32][33];
    __shared__ float Bs[32][33];
    int tid = threadIdx.x;
    int m0 = blockIdx.y * 32, n0 = blockIdx.x * 32;
    int lr = tid >> 3, lk = (tid & 7) << 2;
    int ty = tid >> 4, tx = tid & 15;
    float acc00 = 0.f, acc01 = 0.f, acc10 = 0.f, acc11 = 0.f;
    for (int kk = 0; kk < HH; kk += 32) {
        float4 a = *(const float4*)(g_WkT + (m0 + lr) * HH + kk + lk);
        float4 b = *(const float4*)(g_WqT + (n0 + lr) * HH + kk + lk);
        __syncthreads();
        As[lk + 0][lr] = a.x; As[lk + 1][lr] = a.y; As[lk + 2][lr] = a.z; As[lk + 3][lr] = a.w;
        Bs[lk + 0][lr] = b.x; Bs[lk + 1][lr] = b.y; Bs[lk + 2][lr] = b.z; Bs[lk + 3][lr] = b.w;
        __syncthreads();
#pragma unroll
        for (int k = 0; k < 32; ++k) {
            float a0 = As[k][ty * 2], a1 = As[k][ty * 2 + 1];
            float b0 = Bs[k][tx * 2], b1 = Bs[k][tx * 2 + 1];
            acc00 += a0 * b0; acc01 += a0 * b1;
            acc10 += a1 * b0; acc11 += a1 * b1;
        }
    }
    g_At[(m0 + ty * 2 + 0) * HH + n0 + tx * 2 + 0] = acc00;
    g_At[(m0 + ty * 2 + 0) * HH + n0 + tx * 2 + 1] = acc01;
    g_At[(m0 + ty * 2 + 1) * HH + n0 + tx * 2 + 0] = acc10;
    g_At[(m0 + ty * 2 + 1) * HH + n0 + tx * 2 + 1] = acc11;
}

// ---------------- one-pass online-softmax attention over bf16 hs ----------------
__global__ __launch_bounds__(256) void k_attn() {
    int b = blockIdx.x;
    int tid = threadIdx.x;
    int w = tid >> 5, ln = tid & 31;

    float qf[16];
    {
        const float4* q4 = (const float4*)(g_q2 + b * HH + ln * 16);
#pragma unroll
        for (int i = 0; i < 4; ++i) {
            float4 v = q4[i];
            qf[i * 4 + 0] = v.x; qf[i * 4 + 1] = v.y; qf[i * 4 + 2] = v.z; qf[i * 4 + 3] = v.w;
        }
    }

    float m = -INFINITY, l = 0.f;
    float ca[16];
#pragma unroll
    for (int q = 0; q < 16; ++q) ca[q] = 0.f;

    const __nv_bfloat16* hb0 = g_hsb + ((size_t)w * BB + b) * HH + ln * 16;
    uint4 u0 = *(const uint4*)hb0;
    uint4 u1 = *(const uint4*)(hb0 + 8);

#pragma unroll 4
    for (int it = 0; it < SS / 8; ++it) {
        uint4 c0 = u0, c1 = u1;
        if (it + 1 < SS / 8) {
            const __nv_bfloat16* hb = g_hsb + ((size_t)(w + (it + 1) * 8) * BB + b) * HH + ln * 16;
            u0 = *(const uint4*)hb;
            u1 = *(const uint4*)(hb + 8);
        }
        float f[16];
        {
            const __nv_bfloat162* p0 = (const __nv_bfloat162*)&c0;
            const __nv_bfloat162* p1 = (const __nv_bfloat162*)&c1;
#pragma unroll
            for (int j = 0; j < 4; ++j) {
                float2 t = __bfloat1622float2(p0[j]);
                f[2 * j] = t.x; f[2 * j + 1] = t.y;
                float2 t2 = __bfloat1622float2(p1[j]);
                f[8 + 2 * j] = t2.x; f[8 + 2 * j + 1] = t2.y;
            }
        }
        float dot = 0.f;
#pragma unroll
        for (int q = 0; q < 16; ++q) dot += f[q] * qf[q];
#pragma unroll
        for (int off = 16; off; off >>= 1) dot += __shfl_xor_sync(0xffffffffu, dot, off);
        float mn = fmaxf(m, dot);
        float scl = __expf(m - mn);
        float p = __expf(dot - mn);
        m = mn;
        l = l * scl + p;
#pragma unroll
        for (int q = 0; q < 16; ++q) ca[q] = ca[q] * scl + p * f[q];
    }

    __shared__ float sm[8], sl[8];
    __shared__ float sc[8][HH];
#pragma unroll
    for (int q = 0; q < 16; ++q) sc[w][ln * 16 + q] = ca[q];
    if (ln == 0) { sm[w] = m; sl[w] = l; }
    __syncthreads();

    float M = sm[0];
#pragma unroll
    for (int w2 = 1; w2 < 8; ++w2) M = fmaxf(M, sm[w2]);
    float ew[8];
    float L = 0.f;
#pragma unroll
    for (int w2 = 0; w2 < 8; ++w2) { ew[w2] = __expf(sm[w2] - M); L += sl[w2] * ew[w2]; }
    float invL = 1.f / L;
    for (int h = tid; h < HH; h += 256) {
        float v = 0.f;
#pragma unroll
        for (int w2 = 0; w2 < 8; ++w2) v += ew[w2] * sc[w2][h];
        v *= invL;
        __nv_bfloat16 hi = __float2bfloat16(v);
        g_ctxhi[b * HH + h] = hi;
        g_ctxlo[b * HH + h] = __float2bfloat16(v - __bfloat162float(hi));
    }
}

// ---------------- output projection ----------------
__global__ void k_out(int par, const float* __restrict__ outW, const float* __restrict__ outb,
                      float* __restrict__ out, int t) {
    int tid = threadIdx.x;
    int b = blockIdx.x * 8 + (tid >> 5);
    int ln = tid & 31;
    const float* hp = g_hbuf[par] + b * HH;
    float p = 0.f;
#pragma unroll
    for (int q = 0; q < 16; ++q) p += hp[ln + (q << 5)] * outW[ln + (q << 5)];
#pragma unroll
    for (int off = 16; off; off >>= 1) p += __shfl_xor_sync(0xffffffffu, p, off);
    if (ln == 0) out[b * TT + t] = p + outb[0];
}

// ---------------- host launcher ----------------
extern "C" void kernel_launch(void* const* d_in, const int* in_sizes, int n_in,
                              void* d_out, int out_size) {
    int off = (n_in >= 18 && in_sizes[1] == 1) ? 1 : 0;
    const float* enc_inputs = (const float*)d_in[0];
    const float* embed_W = (const float*)d_in[1 + off];
    const float* embed_b = (const float*)d_in[2 + off];
    const float* enc_Wih = (const float*)d_in[3 + off];
    const float* enc_Whh = (const float*)d_in[4 + off];
    const float* enc_bih = (const float*)d_in[5 + off];
    const float* enc_bhh = (const float*)d_in[6 + off];
    const float* dec_Wih = (const float*)d_in[7 + off];
    const float* dec_Whh = (const float*)d_in[8 + off];
    const float* dec_bih = (const float*)d_in[9 + off];
    const float* dec_bhh = (const float*)d_in[10 + off];
    const float* Wq = (const float*)d_in[11 + off];
    const float* bq = (const float*)d_in[12 + off];
    const float* Wk = (const float*)d_in[13 + off];
    // bk dropped: uniform over s -> softmax-invariant
    const float* out_W = (const float*)d_in[15 + off];
    const float* out_b = (const float*)d_in[16 + off];
    float* out = (float*)d_out;

    float* g_WkT_p; cudaGetSymbolAddress((void**)&g_WkT_p, g_WkT);
    float* g_WqT_p; cudaGetSymbolAddress((void**)&g_WqT_p, g_WqT);

    cudaFuncSetAttribute(lstm_enc_persist, cudaFuncAttributeMaxDynamicSharedMemorySize, PSMEM);
    cudaFuncSetAttribute(lstm_mma_dec, cudaFuncAttributeMaxDynamicSharedMemorySize, SMEM_BYTES);
    cudaFuncSetAttribute(q2_mma, cudaFuncAttributeMaxDynamicSharedMemorySize, SMEM_BYTES);

    // ---- prep ----
    k_zero<<<(BB * HH + 255) / 256, 256>>>();
    k_vu<<<GG / 256, 256>>>(embed_W, embed_b, enc_Wih, enc_bih, enc_bhh);
    k_wenc_split<<<(GG * HH) / 256, 256>>>(enc_Whh);
    k_wdec_split<<<(GG * K2) / 256, 256>>>(dec_Wih, dec_Whh, dec_bih, dec_bhh);
    k_bqk<<<2, 256>>>(bq, Wk);
    dim3 tb(32, 8);
    k_transpose512<<<dim3(16, 16), tb>>>(Wk, g_WkT_p);
    k_transpose512<<<dim3(16, 16), tb>>>(Wq, g_WqT_p);
    k_gemm_At<<<dim3(16, 16), 256>>>();
    k_at_split<<<(HH * HH) / 256, 256>>>();

    // ---- encoder: ONE persistent kernel, 512 internal steps ----
    lstm_enc_persist<<<dim3(32, 4), 512, PSMEM>>>(enc_inputs);

    // ---- decoder: 96 steps ----
    dim3 lgrid(GG / 64, BB / 64);   // 32 x 4
    for (int t = 0; t < TT; ++t) {
        int par = t & 1;
        q2_mma<<<dim3(HH / 64, BB / 64), 512, SMEM_BYTES>>>(par);
        k_attn<<<BB, 256>>>();
        lstm_mma_dec<<<lgrid, 512, SMEM_BYTES>>>(par);
        k_out<<<BB / 8, 256>>>(par ^ 1, out_W, out_b, out, t);
    }
    (void)in_sizes; (void)n_in; (void)out_size;
}